// round 1
// baseline (speedup 1.0000x reference)
#include <cuda_runtime.h>
#include <math.h>

// Problem constants
#define B_  16
#define N_  8192
#define L_  512
#define D_  384
#define FFH 1536        // FF = 4*D
#define MCTX (B_ * N_)  // 131072

// ---------------------------------------------------------------------------
// Scratch (device globals: the sanctioned alloc-free scratch mechanism)
// ---------------------------------------------------------------------------
__device__ float g_bufA[MCTX * D_];          // 192 MB
__device__ float g_bufB[MCTX * D_];          // 192 MB
__device__ float g_kv[MCTX * 2 * D_];        // 384 MB  (K = cols 0..383, V = 384..767)
__device__ float g_sim[(long long)B_ * L_ * N_]; // 268 MB
__device__ float g_qn[L_ * D_];
__device__ float g_q[L_ * D_];
__device__ float g_x1[B_ * L_ * D_];
__device__ float g_fn[B_ * L_ * D_];
__device__ float g_f1[B_ * L_ * 2 * FFH];    // 100 MB
__device__ float g_gg[B_ * L_ * FFH];        // 50 MB

// ---------------------------------------------------------------------------
// Generic tiled GEMM: C = act(scale * A@B + bias) + res
// 128x128 tile, BK=16, 256 threads, 8x8 per thread. All dims assumed
// multiples of tile sizes (true for every call in this problem).
// ACT: 0 = none, 1 = relu.
// res_mod: if >0, residual row index = m % res_mod (query broadcast).
// ---------------------------------------------------------------------------
template<int ACT>
__global__ void __launch_bounds__(256)
gemm_nn(const float* __restrict__ A, int lda, long long sA,
        const float* __restrict__ B, int ldb, long long sB,
        float* __restrict__ C, int ldc, long long sC,
        int K, const float* __restrict__ bias,
        const float* __restrict__ res, int res_mod, int res_ld,
        float scale)
{
    __shared__ float As[16][132];
    __shared__ float Bs[16][132];
    A += blockIdx.z * sA; B += blockIdx.z * sB; C += blockIdx.z * sC;
    const int m0 = blockIdx.y * 128, n0 = blockIdx.x * 128;
    const int tid = threadIdx.x;
    const int tx = tid & 15, ty = tid >> 4;

    float acc[8][8];
    #pragma unroll
    for (int i = 0; i < 8; i++)
        #pragma unroll
        for (int j = 0; j < 8; j++) acc[i][j] = 0.f;

    for (int k0 = 0; k0 < K; k0 += 16) {
        #pragma unroll
        for (int r = 0; r < 2; r++) {
            int f = tid + r * 256;
            int row = f >> 2, kc = (f & 3) << 2;
            float4 v = *(const float4*)(A + (long long)(m0 + row) * lda + k0 + kc);
            As[kc + 0][row] = v.x; As[kc + 1][row] = v.y;
            As[kc + 2][row] = v.z; As[kc + 3][row] = v.w;
        }
        #pragma unroll
        for (int r = 0; r < 2; r++) {
            int f = tid + r * 256;
            int kr = f >> 5, nc = (f & 31) << 2;
            float4 v = *(const float4*)(B + (long long)(k0 + kr) * ldb + n0 + nc);
            *(float4*)&Bs[kr][nc] = v;
        }
        __syncthreads();
        #pragma unroll
        for (int kk = 0; kk < 16; kk++) {
            float4 a0 = *(float4*)&As[kk][ty * 8];
            float4 a1 = *(float4*)&As[kk][ty * 8 + 4];
            float4 b0 = *(float4*)&Bs[kk][tx * 8];
            float4 b1 = *(float4*)&Bs[kk][tx * 8 + 4];
            float a[8] = {a0.x, a0.y, a0.z, a0.w, a1.x, a1.y, a1.z, a1.w};
            float b[8] = {b0.x, b0.y, b0.z, b0.w, b1.x, b1.y, b1.z, b1.w};
            #pragma unroll
            for (int i = 0; i < 8; i++)
                #pragma unroll
                for (int j = 0; j < 8; j++)
                    acc[i][j] = fmaf(a[i], b[j], acc[i][j]);
        }
        __syncthreads();
    }

    #pragma unroll
    for (int i = 0; i < 8; i++) {
        int m = m0 + ty * 8 + i;
        long long crow = (long long)m * ldc;
        const float* rr = res ? res + (long long)(res_mod ? (m % res_mod) : m) * res_ld
                              : (const float*)0;
        #pragma unroll
        for (int jj = 0; jj < 2; jj++) {
            int n = n0 + tx * 8 + jj * 4;
            float4 v;
            float* vp = &v.x;
            #pragma unroll
            for (int q = 0; q < 4; q++) {
                float val = acc[i][jj * 4 + q] * scale;
                if (bias) val += bias[n + q];
                if (ACT == 1) val = fmaxf(val, 0.f);
                if (rr) val += rr[n + q];
                vp[q] = val;
            }
            *(float4*)(C + crow + n) = v;
        }
    }
}

// C[m,n] = scale * sum_k A[m,k] * B[n,k]   (B row-major [N x K], i.e. A @ B^T)
template<int ACT>
__global__ void __launch_bounds__(256)
gemm_nt(const float* __restrict__ A, int lda, long long sA,
        const float* __restrict__ B, int ldb, long long sB,
        float* __restrict__ C, int ldc, long long sC,
        int K, float scale)
{
    __shared__ float As[16][132];
    __shared__ float Bs[16][132];
    A += blockIdx.z * sA; B += blockIdx.z * sB; C += blockIdx.z * sC;
    const int m0 = blockIdx.y * 128, n0 = blockIdx.x * 128;
    const int tid = threadIdx.x;
    const int tx = tid & 15, ty = tid >> 4;

    float acc[8][8];
    #pragma unroll
    for (int i = 0; i < 8; i++)
        #pragma unroll
        for (int j = 0; j < 8; j++) acc[i][j] = 0.f;

    for (int k0 = 0; k0 < K; k0 += 16) {
        #pragma unroll
        for (int r = 0; r < 2; r++) {
            int f = tid + r * 256;
            int row = f >> 2, kc = (f & 3) << 2;
            float4 v = *(const float4*)(A + (long long)(m0 + row) * lda + k0 + kc);
            As[kc + 0][row] = v.x; As[kc + 1][row] = v.y;
            As[kc + 2][row] = v.z; As[kc + 3][row] = v.w;
        }
        #pragma unroll
        for (int r = 0; r < 2; r++) {
            int f = tid + r * 256;
            int nrow = f >> 2, kc = (f & 3) << 2;
            float4 v = *(const float4*)(B + (long long)(n0 + nrow) * ldb + k0 + kc);
            Bs[kc + 0][nrow] = v.x; Bs[kc + 1][nrow] = v.y;
            Bs[kc + 2][nrow] = v.z; Bs[kc + 3][nrow] = v.w;
        }
        __syncthreads();
        #pragma unroll
        for (int kk = 0; kk < 16; kk++) {
            float4 a0 = *(float4*)&As[kk][ty * 8];
            float4 a1 = *(float4*)&As[kk][ty * 8 + 4];
            float4 b0 = *(float4*)&Bs[kk][tx * 8];
            float4 b1 = *(float4*)&Bs[kk][tx * 8 + 4];
            float a[8] = {a0.x, a0.y, a0.z, a0.w, a1.x, a1.y, a1.z, a1.w};
            float b[8] = {b0.x, b0.y, b0.z, b0.w, b1.x, b1.y, b1.z, b1.w};
            #pragma unroll
            for (int i = 0; i < 8; i++)
                #pragma unroll
                for (int j = 0; j < 8; j++)
                    acc[i][j] = fmaf(a[i], b[j], acc[i][j]);
        }
        __syncthreads();
    }

    #pragma unroll
    for (int i = 0; i < 8; i++) {
        int m = m0 + ty * 8 + i;
        long long crow = (long long)m * ldc;
        #pragma unroll
        for (int jj = 0; jj < 2; jj++) {
            int n = n0 + tx * 8 + jj * 4;
            float4 v;
            v.x = acc[i][jj * 4 + 0] * scale;
            v.y = acc[i][jj * 4 + 1] * scale;
            v.z = acc[i][jj * 4 + 2] * scale;
            v.w = acc[i][jj * 4 + 3] * scale;
            *(float4*)(C + crow + n) = v;
        }
    }
}

// ---------------------------------------------------------------------------
// Point-MLP first layer: out[m,n] = relu(sum_{k<3} x[m,k]*w0[k,n] + b0[n])
// one block per point row, 384 threads
// ---------------------------------------------------------------------------
__global__ void mlp0_kernel(const float* __restrict__ x, const float* __restrict__ w0,
                            const float* __restrict__ b0, float* __restrict__ out)
{
    __shared__ float sw[3 * D_];
    __shared__ float sb[D_];
    for (int i = threadIdx.x; i < 3 * D_; i += blockDim.x) sw[i] = w0[i];
    sb[threadIdx.x] = b0[threadIdx.x];
    __syncthreads();
    long long m = blockIdx.x;
    int n = threadIdx.x;
    float x0 = x[m * 3 + 0], x1 = x[m * 3 + 1], x2 = x[m * 3 + 2];
    float v = fmaf(x0, sw[n], fmaf(x1, sw[D_ + n], fmaf(x2, sw[2 * D_ + n], sb[n])));
    out[m * D_ + n] = fmaxf(v, 0.f);
}

// ---------------------------------------------------------------------------
// LayerNorm over last dim (384). 128 threads/row, 3 elems/thread.
// ---------------------------------------------------------------------------
__global__ void ln_kernel(const float* __restrict__ in, float* __restrict__ out,
                          const float* __restrict__ gamma, const float* __restrict__ beta)
{
    long long row = blockIdx.x;
    const float* p = in + row * D_;
    float* q = out + row * D_;
    int t = threadIdx.x;
    float v0 = p[t], v1 = p[t + 128], v2 = p[t + 256];
    float s = v0 + v1 + v2;
    float sq = v0 * v0 + v1 * v1 + v2 * v2;
    #pragma unroll
    for (int o = 16; o; o >>= 1) {
        s += __shfl_xor_sync(0xffffffffu, s, o);
        sq += __shfl_xor_sync(0xffffffffu, sq, o);
    }
    __shared__ float rs[4], rq[4];
    if ((t & 31) == 0) { rs[t >> 5] = s; rq[t >> 5] = sq; }
    __syncthreads();
    float S = rs[0] + rs[1] + rs[2] + rs[3];
    float Q = rq[0] + rq[1] + rq[2] + rq[3];
    float mean = S * (1.f / (float)D_);
    float var = Q * (1.f / (float)D_) - mean * mean;
    float inv = rsqrtf(var + 1e-5f);
    q[t]       = (v0 - mean) * inv * gamma[t]       + beta[t];
    q[t + 128] = (v1 - mean) * inv * gamma[t + 128] + beta[t + 128];
    q[t + 256] = (v2 - mean) * inv * gamma[t + 256] + beta[t + 256];
}

// ---------------------------------------------------------------------------
// Row softmax over 8192-wide rows (in place). One block/row, row in smem.
// ---------------------------------------------------------------------------
__global__ void softmax_kernel(float* __restrict__ sim)
{
    extern __shared__ float sd[];
    __shared__ float red[8];
    long long row = blockIdx.x;
    float* p = sim + row * (long long)N_;
    int t = threadIdx.x;
    float mx = -3.4e38f;
    for (int i = t; i < N_; i += 256) { float v = p[i]; sd[i] = v; mx = fmaxf(mx, v); }
    #pragma unroll
    for (int o = 16; o; o >>= 1) mx = fmaxf(mx, __shfl_xor_sync(0xffffffffu, mx, o));
    if ((t & 31) == 0) red[t >> 5] = mx;
    __syncthreads();
    mx = red[0];
    #pragma unroll
    for (int w = 1; w < 8; w++) mx = fmaxf(mx, red[w]);
    float sum = 0.f;
    for (int i = t; i < N_; i += 256) { float e = __expf(sd[i] - mx); sd[i] = e; sum += e; }
    #pragma unroll
    for (int o = 16; o; o >>= 1) sum += __shfl_xor_sync(0xffffffffu, sum, o);
    __syncthreads();
    if ((t & 31) == 0) red[t >> 5] = sum;
    __syncthreads();
    sum = 0.f;
    #pragma unroll
    for (int w = 0; w < 8; w++) sum += red[w];
    float inv = 1.f / sum;
    for (int i = t; i < N_; i += 256) p[i] = sd[i] * inv;
}

// ---------------------------------------------------------------------------
// GEGLU: out[m,j] = f1[m,j] * gelu_exact(f1[m, FFH+j])
// ---------------------------------------------------------------------------
__global__ void geglu_kernel(const float* __restrict__ f1, float* __restrict__ out)
{
    long long idx = (long long)blockIdx.x * 256 + threadIdx.x;
    long long m = idx / FFH;
    int j = (int)(idx - m * FFH);
    float a = f1[m * (2 * FFH) + j];
    float g = f1[m * (2 * FFH) + FFH + j];
    float ge = 0.5f * g * (1.f + erff(g * 0.70710678118654752440f));
    out[idx] = a * ge;
}

// ---------------------------------------------------------------------------
// Launch
// ---------------------------------------------------------------------------
extern "C" void kernel_launch(void* const* d_in, const int* in_sizes, int n_in,
                              void* d_out, int out_size)
{
    const float* x       = (const float*)d_in[0];
    const float* mlp_w0  = (const float*)d_in[1];
    const float* mlp_b0  = (const float*)d_in[2];
    const float* mlp_w1  = (const float*)d_in[3];
    const float* mlp_b1  = (const float*)d_in[4];
    const float* mlp_w2  = (const float*)d_in[5];
    const float* mlp_b2  = (const float*)d_in[6];
    const float* mlp_w3  = (const float*)d_in[7];
    const float* mlp_b3  = (const float*)d_in[8];
    const float* query   = (const float*)d_in[9];
    const float* ln_q_g  = (const float*)d_in[10];
    const float* ln_q_b  = (const float*)d_in[11];
    const float* ln_ctx_g = (const float*)d_in[12];
    const float* ln_ctx_b = (const float*)d_in[13];
    const float* wq      = (const float*)d_in[14];
    const float* wkv     = (const float*)d_in[15];
    const float* wo      = (const float*)d_in[16];
    const float* bo      = (const float*)d_in[17];
    const float* ln_ff_g = (const float*)d_in[18];
    const float* ln_ff_b = (const float*)d_in[19];
    const float* ff_w1   = (const float*)d_in[20];
    const float* ff_b1   = (const float*)d_in[21];
    const float* ff_w2   = (const float*)d_in[22];
    const float* ff_b2   = (const float*)d_in[23];

    // Resolve scratch symbol addresses once (first call = correctness run,
    // outside graph capture). Capture call sees only kernel launches.
    static float *bA = 0, *bB = 0, *kv = 0, *sim = 0, *qn = 0, *qq = 0,
                 *x1 = 0, *fn = 0, *f1 = 0, *gg = 0;
    if (!bA) {
        cudaGetSymbolAddress((void**)&bA, g_bufA);
        cudaGetSymbolAddress((void**)&bB, g_bufB);
        cudaGetSymbolAddress((void**)&kv, g_kv);
        cudaGetSymbolAddress((void**)&sim, g_sim);
        cudaGetSymbolAddress((void**)&qn, g_qn);
        cudaGetSymbolAddress((void**)&qq, g_q);
        cudaGetSymbolAddress((void**)&x1, g_x1);
        cudaGetSymbolAddress((void**)&fn, g_fn);
        cudaGetSymbolAddress((void**)&f1, g_f1);
        cudaGetSymbolAddress((void**)&gg, g_gg);
    }

    // 1) point MLP layer 0 (K=3)
    mlp0_kernel<<<MCTX, D_>>>(x, mlp_w0, mlp_b0, bA);

    // 2-4) MLP layers 1-3 (D x D), relu on 1,2
    dim3 gMLP(D_ / 128, MCTX / 128);
    gemm_nn<1><<<gMLP, 256>>>(bA, D_, 0, mlp_w1, D_, 0, bB, D_, 0, D_, mlp_b1, 0, 0, 0, 1.f);
    gemm_nn<1><<<gMLP, 256>>>(bB, D_, 0, mlp_w2, D_, 0, bA, D_, 0, D_, mlp_b2, 0, 0, 0, 1.f);
    gemm_nn<0><<<gMLP, 256>>>(bA, D_, 0, mlp_w3, D_, 0, bB, D_, 0, D_, mlp_b3, 0, 0, 0, 1.f);

    // 5) LN(ctx) -> bA
    ln_kernel<<<MCTX, 128>>>(bB, bA, ln_ctx_g, ln_ctx_b);

    // 6) KV = CN @ wkv  [MCTX x 768]
    dim3 gKV(2 * D_ / 128, MCTX / 128);
    gemm_nn<0><<<gKV, 256>>>(bA, D_, 0, wkv, 2 * D_, 0, kv, 2 * D_, 0, D_, 0, 0, 0, 0, 1.f);

    // 7-8) Q path (shared across batch)
    ln_kernel<<<L_, 128>>>(query, qn, ln_q_g, ln_q_b);
    dim3 gQ(D_ / 128, L_ / 128);
    gemm_nn<0><<<gQ, 256>>>(qn, D_, 0, wq, D_, 0, qq, D_, 0, D_, 0, 0, 0, 0, 1.f);

    // 9) sim[b] = Q @ K[b]^T * scale
    dim3 gS(N_ / 128, L_ / 128, B_);
    gemm_nt<0><<<gS, 256>>>(qq, D_, 0, kv, 2 * D_, (long long)N_ * 2 * D_,
                            sim, N_, (long long)L_ * N_, D_, 0.05103103630798288f);

    // 10) softmax rows
    softmax_kernel<<<B_ * L_, 256, N_ * sizeof(float)>>>(sim);

    // 11) out[b] = attn[b] @ V[b]  -> bA as [B*L, D]
    dim3 gAV(D_ / 128, L_ / 128, B_);
    gemm_nn<0><<<gAV, 256>>>(sim, N_, (long long)L_ * N_, kv + D_, 2 * D_, (long long)N_ * 2 * D_,
                             bA, D_, (long long)L_ * D_, N_, 0, 0, 0, 0, 1.f);

    // 12) x1 = out @ wo + bo + broadcast(query)
    dim3 gO(D_ / 128, B_ * L_ / 128);
    gemm_nn<0><<<gO, 256>>>(bA, D_, 0, wo, D_, 0, x1, D_, 0, D_, bo, query, L_, D_, 1.f);

    // 13) LN(x1) -> fn
    ln_kernel<<<B_ * L_, 128>>>(x1, fn, ln_ff_g, ln_ff_b);

    // 14) f1 = fn @ ff_w1 + ff_b1  [B*L x 3072]
    dim3 gF1(2 * FFH / 128, B_ * L_ / 128);
    gemm_nn<0><<<gF1, 256>>>(fn, D_, 0, ff_w1, 2 * FFH, 0, f1, 2 * FFH, 0, D_, ff_b1, 0, 0, 0, 1.f);

    // 15) GEGLU
    geglu_kernel<<<(B_ * L_ * FFH) / 256, 256>>>(f1, gg);

    // 16) out = gg @ ff_w2 + ff_b2 + x1
    dim3 gF2(D_ / 128, B_ * L_ / 128);
    gemm_nn<0><<<gF2, 256>>>(gg, FFH, 0, ff_w2, D_, 0, (float*)d_out, D_, 0, FFH,
                             ff_b2, x1, 0, D_, 1.f);
}

// round 3
// speedup vs baseline: 1.3744x; 1.3744x over previous
#include <cuda_runtime.h>
#include <cuda_bf16.h>
#include <math.h>
#include <stdint.h>

#define B_  16
#define N_  8192
#define L_  512
#define D_  384
#define FFH 1536
#define MCTX (B_ * N_)

// ---------------------------------------------------------------------------
// Scratch
// ---------------------------------------------------------------------------
__device__ float g_bufA[MCTX * D_];
__device__ float g_bufB[MCTX * D_];              // reused as V^T later
__device__ float g_kv[MCTX * 2 * D_];
__device__ float g_sim[(long long)B_ * L_ * N_];
__device__ float g_qn[L_ * D_];
__device__ float g_q[L_ * D_];
__device__ float g_x1[B_ * L_ * D_];
__device__ float g_fn[B_ * L_ * D_];
__device__ float g_f1[B_ * L_ * 2 * FFH];
__device__ float g_gg[B_ * L_ * FFH];

// split-bf16 weights, transposed to [N,K]
#define W1OFF   0
#define W2OFF   147456
#define W3OFF   294912
#define WQOFF   442368
#define WKVOFF  589824
#define WOOFF   884736
#define FF1OFF  1032192
#define FF2OFF  2211840
#define WTOT    2801664
__device__ __nv_bfloat16 g_whi[WTOT];
__device__ __nv_bfloat16 g_wlo[WTOT];

// ---------------------------------------------------------------------------
// helpers
// ---------------------------------------------------------------------------
__device__ __forceinline__ uint32_t smem_u32(const void* p) {
    uint32_t a;
    asm("{ .reg .u64 t; cvta.to.shared.u64 t, %1; cvt.u32.u64 %0, t; }" : "=r"(a) : "l"(p));
    return a;
}
__device__ __forceinline__ void ldsm4(uint32_t* r, uint32_t addr) {
    asm volatile("ldmatrix.sync.aligned.m8n8.x4.shared.b16 {%0,%1,%2,%3}, [%4];"
        : "=r"(r[0]), "=r"(r[1]), "=r"(r[2]), "=r"(r[3]) : "r"(addr));
}
__device__ __forceinline__ void mma16816(float* c, const uint32_t* a, const uint32_t* b) {
    asm volatile("mma.sync.aligned.m16n8k16.row.col.f32.bf16.bf16.f32 "
        "{%0,%1,%2,%3}, {%4,%5,%6,%7}, {%8,%9}, {%0,%1,%2,%3};"
        : "+f"(c[0]), "+f"(c[1]), "+f"(c[2]), "+f"(c[3])
        : "r"(a[0]), "r"(a[1]), "r"(a[2]), "r"(a[3]), "r"(b[0]), "r"(b[1]));
}
__device__ __forceinline__ uint32_t b2u(__nv_bfloat162 h) {
    return *reinterpret_cast<uint32_t*>(&h);
}
// 8 fp32 -> hi/lo bf16x8
__device__ __forceinline__ void cvt8(const float4 v0, const float4 v1, uint4& hi, uint4& lo) {
    __nv_bfloat162 h0 = __float22bfloat162_rn(make_float2(v0.x, v0.y));
    __nv_bfloat162 h1 = __float22bfloat162_rn(make_float2(v0.z, v0.w));
    __nv_bfloat162 h2 = __float22bfloat162_rn(make_float2(v1.x, v1.y));
    __nv_bfloat162 h3 = __float22bfloat162_rn(make_float2(v1.z, v1.w));
    __nv_bfloat162 l0 = __float22bfloat162_rn(make_float2(
        v0.x - __bfloat162float(h0.x), v0.y - __bfloat162float(h0.y)));
    __nv_bfloat162 l1 = __float22bfloat162_rn(make_float2(
        v0.z - __bfloat162float(h1.x), v0.w - __bfloat162float(h1.y)));
    __nv_bfloat162 l2 = __float22bfloat162_rn(make_float2(
        v1.x - __bfloat162float(h2.x), v1.y - __bfloat162float(h2.y)));
    __nv_bfloat162 l3 = __float22bfloat162_rn(make_float2(
        v1.z - __bfloat162float(h3.x), v1.w - __bfloat162float(h3.y)));
    hi = make_uint4(b2u(h0), b2u(h1), b2u(h2), b2u(h3));
    lo = make_uint4(b2u(l0), b2u(l1), b2u(l2), b2u(l3));
}

// smem layout per stage (32 KB):
//   A_hi @ 0, A_lo @ 8192, B_hi @ 16384, B_lo @ 24576
// each array: [128 rows][32 k] bf16 stored as 8x8 blocks:
//   off(row,k) = (row>>3)*512 + (k>>3)*128 + (row&7)*16 + (k&7)*2
#define STAGE_BYTES 32768
#define SMEM_BYTES  65536

// ---------------------------------------------------------------------------
// split-bf16 mma.sync GEMM: C[M,N] = epi(scale * A[M,K] @ Bt[N,K]^T)
// ---------------------------------------------------------------------------
template<int BSPLIT>
__global__ void __launch_bounds__(256, 1)
gemm_mma(const float* __restrict__ A, int lda, long long sA,
         const float* __restrict__ Bf,
         const __nv_bfloat16* __restrict__ Bhi, const __nv_bfloat16* __restrict__ Blo,
         int ldb, long long sB,
         float* __restrict__ C, int ldc, long long sC,
         int K, const float* __restrict__ bias, int relu,
         const float* __restrict__ res, int res_mod, int res_ld, float scale)
{
    extern __shared__ __align__(128) char smem[];
    const int tid = threadIdx.x, lane = tid & 31, warp = tid >> 5;
    A += blockIdx.z * sA;
    if (BSPLIT) { Bhi += blockIdx.z * sB; Blo += blockIdx.z * sB; }
    else        { Bf  += blockIdx.z * sB; }
    C += blockIdx.z * sC;
    const int m0 = blockIdx.y * 128, n0 = blockIdx.x * 128;
    const int wm0 = (warp >> 1) * 32, wn0 = (warp & 1) * 64;

    // staging mapping: thread handles (row r, kb0) and (row r, kb0+2)
    const int r = tid & 127;
    const int kb0 = tid >> 7;   // 0 or 1
    const float* gA = A + (long long)(m0 + r) * lda + kb0 * 8;
    const float* gB = 0;
    const __nv_bfloat16 *gBh = 0, *gBl = 0;
    if (BSPLIT) {
        gBh = Bhi + (long long)(n0 + r) * ldb + kb0 * 8;
        gBl = Blo + (long long)(n0 + r) * ldb + kb0 * 8;
    } else {
        gB = Bf + (long long)(n0 + r) * ldb + kb0 * 8;
    }
    const int sts0 = (r >> 3) * 512 + (r & 7) * 16 + kb0 * 128; // unit0; unit1 = +256
    uint32_t sb = smem_u32(smem);

    // ldmatrix per-thread offsets
    const int la = lane & 15;
    const int rA = wm0 + la;
    const int offA0 = (rA >> 3) * 512 + (rA & 7) * 16 + (lane >> 4) * 128;
    const int nB = wn0 + (lane >> 4) * 8 + (lane & 7);
    const int offB0 = (nB >> 3) * 512 + (nB & 7) * 16 + ((lane >> 3) & 1) * 128;

    float acc[2][8][4];
    #pragma unroll
    for (int i = 0; i < 2; i++)
        #pragma unroll
        for (int j = 0; j < 8; j++)
            #pragma unroll
            for (int q = 0; q < 4; q++) acc[i][j][q] = 0.f;

    const int KC = K >> 5;
    uint4 sAh[2], sAl[2], sBh[2], sBl[2];

#define GLOAD(kc) do {                                                          \
    const float* pa = gA + (long long)(kc) * 32;                                \
    cvt8(*(const float4*)pa, *(const float4*)(pa + 4), sAh[0], sAl[0]);         \
    cvt8(*(const float4*)(pa + 16), *(const float4*)(pa + 20), sAh[1], sAl[1]); \
    if (BSPLIT) {                                                               \
        const __nv_bfloat16* ph = gBh + (long long)(kc) * 32;                   \
        const __nv_bfloat16* pl = gBl + (long long)(kc) * 32;                   \
        sBh[0] = *(const uint4*)ph;  sBh[1] = *(const uint4*)(ph + 16);         \
        sBl[0] = *(const uint4*)pl;  sBl[1] = *(const uint4*)(pl + 16);         \
    } else {                                                                    \
        const float* pb = gB + (long long)(kc) * 32;                            \
        cvt8(*(const float4*)pb, *(const float4*)(pb + 4), sBh[0], sBl[0]);     \
        cvt8(*(const float4*)(pb + 16), *(const float4*)(pb + 20), sBh[1], sBl[1]); \
    }                                                                           \
} while (0)

#define SSTORE(stg) do {                                                        \
    char* st = smem + (stg) * STAGE_BYTES;                                      \
    *(uint4*)(st + sts0)                 = sAh[0];                              \
    *(uint4*)(st + sts0 + 256)           = sAh[1];                              \
    *(uint4*)(st + 8192 + sts0)          = sAl[0];                              \
    *(uint4*)(st + 8192 + sts0 + 256)    = sAl[1];                              \
    *(uint4*)(st + 16384 + sts0)         = sBh[0];                              \
    *(uint4*)(st + 16384 + sts0 + 256)   = sBh[1];                              \
    *(uint4*)(st + 24576 + sts0)         = sBl[0];                              \
    *(uint4*)(st + 24576 + sts0 + 256)   = sBl[1];                              \
} while (0)

    GLOAD(0);
    SSTORE(0);
    __syncthreads();

    for (int kc = 0; kc < KC; kc++) {
        const int stage = kc & 1;
        if (kc + 1 < KC) GLOAD(kc + 1);

        #pragma unroll
        for (int s = 0; s < 2; s++) {
            uint32_t base = sb + stage * STAGE_BYTES + s * 256;
            uint32_t ah[2][4], al[2][4], bh[4], bl[4];
            ldsm4(ah[0], base + offA0);
            ldsm4(ah[1], base + offA0 + 1024);
            ldsm4(al[0], base + 8192 + offA0);
            ldsm4(al[1], base + 8192 + offA0 + 1024);
            #pragma unroll
            for (int p = 0; p < 4; p++) {
                ldsm4(bh, base + 16384 + offB0 + p * 1024);
                ldsm4(bl, base + 24576 + offB0 + p * 1024);
                #pragma unroll
                for (int mt = 0; mt < 2; mt++) {
                    mma16816(acc[mt][2 * p],     ah[mt], bh);
                    mma16816(acc[mt][2 * p],     al[mt], bh);
                    mma16816(acc[mt][2 * p],     ah[mt], bl);
                    mma16816(acc[mt][2 * p + 1], ah[mt], bh + 2);
                    mma16816(acc[mt][2 * p + 1], al[mt], bh + 2);
                    mma16816(acc[mt][2 * p + 1], ah[mt], bl + 2);
                }
            }
        }

        if (kc + 1 < KC) {
            SSTORE((kc + 1) & 1);
            __syncthreads();
        }
    }

    // epilogue
    #pragma unroll
    for (int mt = 0; mt < 2; mt++) {
        #pragma unroll
        for (int nt = 0; nt < 8; nt++) {
            int rr = m0 + wm0 + mt * 16 + (lane >> 2);
            int cc = n0 + wn0 + nt * 8 + (lane & 3) * 2;
            float b0 = bias ? bias[cc] : 0.f;
            float b1 = bias ? bias[cc + 1] : 0.f;
            #pragma unroll
            for (int h = 0; h < 2; h++) {
                int rrow = rr + h * 8;
                float v0 = acc[mt][nt][2 * h + 0] * scale + b0;
                float v1 = acc[mt][nt][2 * h + 1] * scale + b1;
                if (relu) { v0 = fmaxf(v0, 0.f); v1 = fmaxf(v1, 0.f); }
                if (res) {
                    const float* rp = res + (long long)(res_mod ? (rrow % res_mod) : rrow) * res_ld + cc;
                    v0 += rp[0]; v1 += rp[1];
                }
                *(float2*)(C + (long long)rrow * ldc + cc) = make_float2(v0, v1);
            }
        }
    }
#undef GLOAD
#undef SSTORE
}

// ---------------------------------------------------------------------------
// Weight transpose + split: W[K,N] fp32 -> Whi/Wlo[N,K] bf16
// ---------------------------------------------------------------------------
__global__ void wsplit(const float* __restrict__ W, int K, int N,
                       __nv_bfloat16* __restrict__ hi, __nv_bfloat16* __restrict__ lo)
{
    __shared__ float t[32][33];
    int n0 = blockIdx.x * 32, k0 = blockIdx.y * 32;
    int tx = threadIdx.x, ty = threadIdx.y;
    for (int r = ty; r < 32; r += 8) t[r][tx] = W[(long long)(k0 + r) * N + n0 + tx];
    __syncthreads();
    for (int r = ty; r < 32; r += 8) {
        float v = t[tx][r];
        __nv_bfloat16 h = __float2bfloat16(v);
        __nv_bfloat16 l = __float2bfloat16(v - __bfloat162float(h));
        long long o = (long long)(n0 + r) * K + k0 + tx;
        hi[o] = h; lo[o] = l;
    }
}

// V transpose: kv[B*N, 768] (cols 384..767) -> vt[B, 384, 8192] fp32
__global__ void vtrans(const float* __restrict__ kv, float* __restrict__ vt)
{
    __shared__ float t[32][33];
    int n0 = blockIdx.x * 32, d0 = blockIdx.y * 32, b = blockIdx.z;
    int tx = threadIdx.x, ty = threadIdx.y;
    const float* src = kv + (long long)b * N_ * 768 + D_;
    for (int r = ty; r < 32; r += 8) t[r][tx] = src[(long long)(n0 + r) * 768 + d0 + tx];
    __syncthreads();
    float* dst = vt + (long long)b * D_ * N_;
    for (int r = ty; r < 32; r += 8) dst[(long long)(d0 + r) * N_ + n0 + tx] = t[tx][r];
}

// ---------------------------------------------------------------------------
// small fp32 kernels
// ---------------------------------------------------------------------------
__global__ void mlp0_kernel(const float* __restrict__ x, const float* __restrict__ w0,
                            const float* __restrict__ b0, float* __restrict__ out)
{
    __shared__ float sw[3 * D_];
    __shared__ float sbv[D_];
    for (int i = threadIdx.x; i < 3 * D_; i += blockDim.x) sw[i] = w0[i];
    sbv[threadIdx.x] = b0[threadIdx.x];
    __syncthreads();
    long long m = blockIdx.x;
    int n = threadIdx.x;
    float x0 = x[m * 3 + 0], x1 = x[m * 3 + 1], x2 = x[m * 3 + 2];
    float v = fmaf(x0, sw[n], fmaf(x1, sw[D_ + n], fmaf(x2, sw[2 * D_ + n], sbv[n])));
    out[m * D_ + n] = fmaxf(v, 0.f);
}

__global__ void ln_kernel(const float* __restrict__ in, float* __restrict__ out,
                          const float* __restrict__ gamma, const float* __restrict__ beta)
{
    long long row = blockIdx.x;
    const float* p = in + row * D_;
    float* q = out + row * D_;
    int t = threadIdx.x;
    float v0 = p[t], v1 = p[t + 128], v2 = p[t + 256];
    float s = v0 + v1 + v2;
    float sq = v0 * v0 + v1 * v1 + v2 * v2;
    #pragma unroll
    for (int o = 16; o; o >>= 1) {
        s += __shfl_xor_sync(0xffffffffu, s, o);
        sq += __shfl_xor_sync(0xffffffffu, sq, o);
    }
    __shared__ float rs[4], rq[4];
    if ((t & 31) == 0) { rs[t >> 5] = s; rq[t >> 5] = sq; }
    __syncthreads();
    float S = rs[0] + rs[1] + rs[2] + rs[3];
    float Q = rq[0] + rq[1] + rq[2] + rq[3];
    float mean = S * (1.f / (float)D_);
    float var = Q * (1.f / (float)D_) - mean * mean;
    float inv = rsqrtf(var + 1e-5f);
    q[t]       = (v0 - mean) * inv * gamma[t]       + beta[t];
    q[t + 128] = (v1 - mean) * inv * gamma[t + 128] + beta[t + 128];
    q[t + 256] = (v2 - mean) * inv * gamma[t + 256] + beta[t + 256];
}

__global__ void softmax_kernel(float* __restrict__ sim)
{
    extern __shared__ float sd[];
    __shared__ float red[8];
    long long row = blockIdx.x;
    float* p = sim + row * (long long)N_;
    int t = threadIdx.x;
    float mx = -3.4e38f;
    for (int i = t; i < N_; i += 256) { float v = p[i]; sd[i] = v; mx = fmaxf(mx, v); }
    #pragma unroll
    for (int o = 16; o; o >>= 1) mx = fmaxf(mx, __shfl_xor_sync(0xffffffffu, mx, o));
    if ((t & 31) == 0) red[t >> 5] = mx;
    __syncthreads();
    mx = red[0];
    #pragma unroll
    for (int w = 1; w < 8; w++) mx = fmaxf(mx, red[w]);
    float sum = 0.f;
    for (int i = t; i < N_; i += 256) { float e = __expf(sd[i] - mx); sd[i] = e; sum += e; }
    #pragma unroll
    for (int o = 16; o; o >>= 1) sum += __shfl_xor_sync(0xffffffffu, sum, o);
    __syncthreads();
    if ((t & 31) == 0) red[t >> 5] = sum;
    __syncthreads();
    sum = 0.f;
    #pragma unroll
    for (int w = 0; w < 8; w++) sum += red[w];
    float inv = 1.f / sum;
    for (int i = t; i < N_; i += 256) p[i] = sd[i] * inv;
}

__global__ void geglu_kernel(const float* __restrict__ f1, float* __restrict__ out)
{
    long long idx = (long long)blockIdx.x * 256 + threadIdx.x;
    long long m = idx / FFH;
    int j = (int)(idx - m * FFH);
    float a = f1[m * (2 * FFH) + j];
    float g = f1[m * (2 * FFH) + FFH + j];
    float ge = 0.5f * g * (1.f + erff(g * 0.70710678118654752440f));
    out[idx] = a * ge;
}

// ---------------------------------------------------------------------------
// Launch
// ---------------------------------------------------------------------------
extern "C" void kernel_launch(void* const* d_in, const int* in_sizes, int n_in,
                              void* d_out, int out_size)
{
    const float* x        = (const float*)d_in[0];
    const float* mlp_w0   = (const float*)d_in[1];
    const float* mlp_b0   = (const float*)d_in[2];
    const float* mlp_w1   = (const float*)d_in[3];
    const float* mlp_b1   = (const float*)d_in[4];
    const float* mlp_w2   = (const float*)d_in[5];
    const float* mlp_b2   = (const float*)d_in[6];
    const float* mlp_w3   = (const float*)d_in[7];
    const float* mlp_b3   = (const float*)d_in[8];
    const float* query    = (const float*)d_in[9];
    const float* ln_q_g   = (const float*)d_in[10];
    const float* ln_q_b   = (const float*)d_in[11];
    const float* ln_ctx_g = (const float*)d_in[12];
    const float* ln_ctx_b = (const float*)d_in[13];
    const float* wq       = (const float*)d_in[14];
    const float* wkv      = (const float*)d_in[15];
    const float* wo       = (const float*)d_in[16];
    const float* bo       = (const float*)d_in[17];
    const float* ln_ff_g  = (const float*)d_in[18];
    const float* ln_ff_b  = (const float*)d_in[19];
    const float* ff_w1    = (const float*)d_in[20];
    const float* ff_b1    = (const float*)d_in[21];
    const float* ff_w2    = (const float*)d_in[22];
    const float* ff_b2    = (const float*)d_in[23];

    static float *bA = 0, *bB = 0, *kv = 0, *sim = 0, *qn = 0, *qq = 0,
                 *x1 = 0, *fn = 0, *f1 = 0, *gg = 0;
    static __nv_bfloat16 *whi = 0, *wlo = 0;
    if (!bA) {
        cudaGetSymbolAddress((void**)&bA, g_bufA);
        cudaGetSymbolAddress((void**)&bB, g_bufB);
        cudaGetSymbolAddress((void**)&kv, g_kv);
        cudaGetSymbolAddress((void**)&sim, g_sim);
        cudaGetSymbolAddress((void**)&qn, g_qn);
        cudaGetSymbolAddress((void**)&qq, g_q);
        cudaGetSymbolAddress((void**)&x1, g_x1);
        cudaGetSymbolAddress((void**)&fn, g_fn);
        cudaGetSymbolAddress((void**)&f1, g_f1);
        cudaGetSymbolAddress((void**)&gg, g_gg);
        cudaGetSymbolAddress((void**)&whi, g_whi);
        cudaGetSymbolAddress((void**)&wlo, g_wlo);
        cudaFuncSetAttribute(gemm_mma<0>, cudaFuncAttributeMaxDynamicSharedMemorySize, SMEM_BYTES);
        cudaFuncSetAttribute(gemm_mma<1>, cudaFuncAttributeMaxDynamicSharedMemorySize, SMEM_BYTES);
    }
    float* vt = bB;  // reuse

    dim3 tb(32, 8);
    wsplit<<<dim3(12, 12), tb>>>(mlp_w1, D_, D_, whi + W1OFF, wlo + W1OFF);
    wsplit<<<dim3(12, 12), tb>>>(mlp_w2, D_, D_, whi + W2OFF, wlo + W2OFF);
    wsplit<<<dim3(12, 12), tb>>>(mlp_w3, D_, D_, whi + W3OFF, wlo + W3OFF);
    wsplit<<<dim3(12, 12), tb>>>(wq, D_, D_, whi + WQOFF, wlo + WQOFF);
    wsplit<<<dim3(24, 12), tb>>>(wkv, D_, 2 * D_, whi + WKVOFF, wlo + WKVOFF);
    wsplit<<<dim3(12, 12), tb>>>(wo, D_, D_, whi + WOOFF, wlo + WOOFF);
    wsplit<<<dim3(96, 12), tb>>>(ff_w1, D_, 2 * FFH, whi + FF1OFF, wlo + FF1OFF);
    wsplit<<<dim3(12, 48), tb>>>(ff_w2, FFH, D_, whi + FF2OFF, wlo + FF2OFF);

    // point MLP
    mlp0_kernel<<<MCTX, D_>>>(x, mlp_w0, mlp_b0, bA);
    gemm_mma<1><<<dim3(3, MCTX / 128), 256, SMEM_BYTES>>>(
        bA, D_, 0, 0, whi + W1OFF, wlo + W1OFF, D_, 0,
        bB, D_, 0, D_, mlp_b1, 1, 0, 0, 0, 1.f);
    gemm_mma<1><<<dim3(3, MCTX / 128), 256, SMEM_BYTES>>>(
        bB, D_, 0, 0, whi + W2OFF, wlo + W2OFF, D_, 0,
        bA, D_, 0, D_, mlp_b2, 1, 0, 0, 0, 1.f);
    gemm_mma<1><<<dim3(3, MCTX / 128), 256, SMEM_BYTES>>>(
        bA, D_, 0, 0, whi + W3OFF, wlo + W3OFF, D_, 0,
        bB, D_, 0, D_, mlp_b3, 0, 0, 0, 0, 1.f);

    // LN(ctx), KV projection
    ln_kernel<<<MCTX, 128>>>(bB, bA, ln_ctx_g, ln_ctx_b);
    gemm_mma<1><<<dim3(6, MCTX / 128), 256, SMEM_BYTES>>>(
        bA, D_, 0, 0, whi + WKVOFF, wlo + WKVOFF, D_, 0,
        kv, 2 * D_, 0, D_, 0, 0, 0, 0, 0, 1.f);
    vtrans<<<dim3(N_ / 32, D_ / 32, B_), tb>>>(kv, vt);

    // Q path
    ln_kernel<<<L_, 128>>>(query, qn, ln_q_g, ln_q_b);
    gemm_mma<1><<<dim3(3, L_ / 128), 256, SMEM_BYTES>>>(
        qn, D_, 0, 0, whi + WQOFF, wlo + WQOFF, D_, 0,
        qq, D_, 0, D_, 0, 0, 0, 0, 0, 1.f);

    // sim = Q @ K^T * scale
    gemm_mma<0><<<dim3(N_ / 128, L_ / 128, B_), 256, SMEM_BYTES>>>(
        qq, D_, 0, kv, 0, 0, 2 * D_, (long long)N_ * 2 * D_,
        sim, N_, (long long)L_ * N_, D_, 0, 0, 0, 0, 0, 0.05103103630798288f);
    softmax_kernel<<<B_ * L_, 256, N_ * sizeof(float)>>>(sim);

    // out = attn @ V   (V^T as [D][N] fp32 B)
    gemm_mma<0><<<dim3(D_ / 128, L_ / 128, B_), 256, SMEM_BYTES>>>(
        sim, N_, (long long)L_ * N_, vt, 0, 0, N_, (long long)D_ * N_,
        bA, D_, (long long)L_ * D_, N_, 0, 0, 0, 0, 0, 1.f);

    // x1 = out @ wo + bo + broadcast(query)
    gemm_mma<1><<<dim3(3, B_ * L_ / 128), 256, SMEM_BYTES>>>(
        bA, D_, 0, 0, whi + WOOFF, wlo + WOOFF, D_, 0,
        x1, D_, 0, D_, bo, 0, query, L_, D_, 1.f);

    // feedforward
    ln_kernel<<<B_ * L_, 128>>>(x1, fn, ln_ff_g, ln_ff_b);
    gemm_mma<1><<<dim3(24, B_ * L_ / 128), 256, SMEM_BYTES>>>(
        fn, D_, 0, 0, whi + FF1OFF, wlo + FF1OFF, D_, 0,
        f1, 2 * FFH, 0, D_, ff_b1, 0, 0, 0, 0, 1.f);
    geglu_kernel<<<(B_ * L_ * FFH) / 256, 256>>>(f1, gg);
    gemm_mma<1><<<dim3(3, B_ * L_ / 128), 256, SMEM_BYTES>>>(
        gg, FFH, 0, 0, whi + FF2OFF, wlo + FF2OFF, FFH, 0,
        (float*)d_out, D_, 0, FFH, ff_b2, 0, x1, 0, D_, 1.f);
}

// round 4
// speedup vs baseline: 3.8089x; 2.7712x over previous
#include <cuda_runtime.h>
#include <cuda_fp16.h>
#include <math.h>
#include <stdint.h>

#define B_  16
#define N_  8192
#define L_  512
#define D_  384
#define FFH 1536
#define MCTX (B_ * N_)

// ---------------------------------------------------------------------------
// Scratch
// ---------------------------------------------------------------------------
__device__ __half g_h16a[MCTX * D_];
__device__ __half g_h16b[MCTX * D_];            // ctx, later reused as V^T
__device__ __half g_kv16[MCTX * 2 * D_];
__device__ float  g_sim[(long long)B_ * L_ * N_];
__device__ __half g_attn16[(long long)B_ * L_ * N_];
__device__ __half g_qn16[L_ * D_];
__device__ __half g_q16[L_ * D_];
__device__ __half g_av16[B_ * L_ * D_];
__device__ float  g_x1[B_ * L_ * D_];
__device__ __half g_fn16[B_ * L_ * D_];
__device__ __half g_f116[B_ * L_ * 2 * FFH];
__device__ __half g_gg16[B_ * L_ * FFH];

// fp16 weights, transposed to [N,K]
#define W1OFF   0
#define W2OFF   147456
#define W3OFF   294912
#define WQOFF   442368
#define WKVOFF  589824
#define WOOFF   884736
#define FF1OFF  1032192
#define FF2OFF  2211840
#define WTOT    2801664
__device__ __half g_wh[WTOT];

// ---------------------------------------------------------------------------
// helpers
// ---------------------------------------------------------------------------
__device__ __forceinline__ uint32_t smem_u32(const void* p) {
    uint32_t a;
    asm("{ .reg .u64 t; cvta.to.shared.u64 t, %1; cvt.u32.u64 %0, t; }" : "=r"(a) : "l"(p));
    return a;
}
__device__ __forceinline__ void ldsm4(uint32_t* r, uint32_t addr) {
    asm volatile("ldmatrix.sync.aligned.m8n8.x4.shared.b16 {%0,%1,%2,%3}, [%4];"
        : "=r"(r[0]), "=r"(r[1]), "=r"(r[2]), "=r"(r[3]) : "r"(addr));
}
__device__ __forceinline__ void mma16816(float* c, const uint32_t* a, const uint32_t* b) {
    asm volatile("mma.sync.aligned.m16n8k16.row.col.f32.f16.f16.f32 "
        "{%0,%1,%2,%3}, {%4,%5,%6,%7}, {%8,%9}, {%0,%1,%2,%3};"
        : "+f"(c[0]), "+f"(c[1]), "+f"(c[2]), "+f"(c[3])
        : "r"(a[0]), "r"(a[1]), "r"(a[2]), "r"(a[3]), "r"(b[0]), "r"(b[1]));
}
#define CPA16(dst, src) \
    asm volatile("cp.async.cg.shared.global [%0], [%1], 16;" :: "r"(dst), "l"(src))
#define CP_COMMIT() asm volatile("cp.async.commit_group;" ::: "memory")
#define CP_WAIT2()  asm volatile("cp.async.wait_group 2;" ::: "memory")

// smem: 4 stages x 16KB.  Stage: A[128][32] @ 0, B[128][32] @ 8192.
// 8x8 fp16 block layout: off(r,k) = (r>>3)*512 + (k>>3)*128 + (r&7)*16 + (k&7)*2
#define STAGE_BYTES 16384
#define SMEM_BYTES  65536

// ---------------------------------------------------------------------------
// fp16 mma.sync GEMM: C[M,N] = epi(scale * A[M,K] @ Bt[N,K]^T)
// A,B fp16 row-major [M,K]/[N,K]. OUTF16: 1 -> C fp16, 0 -> C fp32.
// ---------------------------------------------------------------------------
template<int OUTF16>
__global__ void __launch_bounds__(256)
gemm_h(const __half* __restrict__ A, int lda, long long sA,
       const __half* __restrict__ B, int ldb, long long sB,
       void* __restrict__ Cv, int ldc, long long sC,
       int K, const float* __restrict__ bias, int relu,
       const float* __restrict__ res, int res_mod, int res_ld, float scale)
{
    extern __shared__ __align__(1024) char smem[];
    const int tid = threadIdx.x, lane = tid & 31, warp = tid >> 5;
    A += blockIdx.z * sA;
    B += blockIdx.z * sB;
    const int m0 = blockIdx.y * 128, n0 = blockIdx.x * 128;
    const int wm0 = (warp >> 1) * 32, wn0 = (warp & 1) * 64;
    uint32_t sb = smem_u32(smem);

    // cp.async assignment: 2 A-transfers + 2 B-transfers of 16B per thread
    const int v0 = tid, v1 = tid + 256;
    const int rA0 = v0 >> 2, kb0 = v0 & 3;
    const int rA1 = v1 >> 2, kb1 = v1 & 3;
    const uint32_t dA0 = (rA0 >> 3) * 512 + kb0 * 128 + (rA0 & 7) * 16;
    const uint32_t dA1 = (rA1 >> 3) * 512 + kb1 * 128 + (rA1 & 7) * 16;
    const __half* pA0 = A + (long long)(m0 + rA0) * lda + kb0 * 8;
    const __half* pA1 = A + (long long)(m0 + rA1) * lda + kb1 * 8;
    const __half* pB0 = B + (long long)(n0 + rA0) * ldb + kb0 * 8;
    const __half* pB1 = B + (long long)(n0 + rA1) * ldb + kb1 * 8;

    // ldmatrix offsets (validated layout)
    const int rA = wm0 + (lane & 15);
    const uint32_t offA0 = (rA >> 3) * 512 + (rA & 7) * 16 + (lane >> 4) * 128;
    const int nB = wn0 + (lane >> 4) * 8 + (lane & 7);
    const uint32_t offB0 = (nB >> 3) * 512 + (nB & 7) * 16 + ((lane >> 3) & 1) * 128;

    float acc[2][8][4];
    #pragma unroll
    for (int i = 0; i < 2; i++)
        #pragma unroll
        for (int j = 0; j < 8; j++)
            #pragma unroll
            for (int q = 0; q < 4; q++) acc[i][j][q] = 0.f;

    const int KC = K >> 5;

#define ISSUE(kc) do {                                                          \
    uint32_t st = sb + ((kc) & 3) * STAGE_BYTES;                                \
    long long ko = (long long)(kc) * 32;                                        \
    CPA16(st + dA0, pA0 + ko);                                                  \
    CPA16(st + dA1, pA1 + ko);                                                  \
    CPA16(st + 8192 + dA0, pB0 + ko);                                           \
    CPA16(st + 8192 + dA1, pB1 + ko);                                           \
} while (0)

    ISSUE(0); CP_COMMIT();
    ISSUE(1); CP_COMMIT();
    ISSUE(2); CP_COMMIT();

    for (int kc = 0; kc < KC; kc++) {
        CP_WAIT2();
        __syncthreads();
        if (kc + 3 < KC) ISSUE(kc + 3);
        CP_COMMIT();

        uint32_t st = sb + (kc & 3) * STAGE_BYTES;
        #pragma unroll
        for (int s = 0; s < 2; s++) {
            uint32_t base = st + s * 256;
            uint32_t ah[2][4], b[4];
            ldsm4(ah[0], base + offA0);
            ldsm4(ah[1], base + offA0 + 1024);
            #pragma unroll
            for (int p = 0; p < 4; p++) {
                ldsm4(b, base + 8192 + offB0 + p * 1024);
                mma16816(acc[0][2 * p],     ah[0], b);
                mma16816(acc[0][2 * p + 1], ah[0], b + 2);
                mma16816(acc[1][2 * p],     ah[1], b);
                mma16816(acc[1][2 * p + 1], ah[1], b + 2);
            }
        }
        __syncthreads();
    }

    // epilogue
    #pragma unroll
    for (int mt = 0; mt < 2; mt++) {
        #pragma unroll
        for (int nt = 0; nt < 8; nt++) {
            int rr = m0 + wm0 + mt * 16 + (lane >> 2);
            int cc = n0 + wn0 + nt * 8 + (lane & 3) * 2;
            float b0 = bias ? bias[cc] : 0.f;
            float b1 = bias ? bias[cc + 1] : 0.f;
            #pragma unroll
            for (int h = 0; h < 2; h++) {
                int rrow = rr + h * 8;
                float v0 = acc[mt][nt][2 * h + 0] * scale + b0;
                float v1 = acc[mt][nt][2 * h + 1] * scale + b1;
                if (relu) { v0 = fmaxf(v0, 0.f); v1 = fmaxf(v1, 0.f); }
                if (res) {
                    const float* rp = res + (long long)(res_mod ? (rrow % res_mod) : rrow) * res_ld + cc;
                    v0 += rp[0]; v1 += rp[1];
                }
                if (OUTF16) {
                    *(__half2*)((__half*)Cv + blockIdx.z * sC + (long long)rrow * ldc + cc) =
                        __floats2half2_rn(v0, v1);
                } else {
                    *(float2*)((float*)Cv + blockIdx.z * sC + (long long)rrow * ldc + cc) =
                        make_float2(v0, v1);
                }
            }
        }
    }
#undef ISSUE
}

// ---------------------------------------------------------------------------
// Weight convert: W[K,N] fp32 -> Wh[N,K] fp16 (transposed)
// ---------------------------------------------------------------------------
__global__ void wcvt(const float* __restrict__ W, int K, int N, __half* __restrict__ out)
{
    __shared__ float t[32][33];
    int n0 = blockIdx.x * 32, k0 = blockIdx.y * 32;
    int tx = threadIdx.x, ty = threadIdx.y;
    for (int r = ty; r < 32; r += 8) t[r][tx] = W[(long long)(k0 + r) * N + n0 + tx];
    __syncthreads();
    for (int r = ty; r < 32; r += 8)
        out[(long long)(n0 + r) * K + k0 + tx] = __float2half_rn(t[tx][r]);
}

// V transpose fp16: kv16[B*N,768] cols 384..767 -> vt[B,384,8192]
__global__ void vtrans(const __half* __restrict__ kv, __half* __restrict__ vt)
{
    __shared__ __half t[32][34];
    int n0 = blockIdx.x * 32, d0 = blockIdx.y * 32, b = blockIdx.z;
    int tx = threadIdx.x, ty = threadIdx.y;
    const __half* src = kv + (long long)b * N_ * 768 + D_;
    for (int r = ty; r < 32; r += 8) t[r][tx] = src[(long long)(n0 + r) * 768 + d0 + tx];
    __syncthreads();
    __half* dst = vt + (long long)b * D_ * N_;
    for (int r = ty; r < 32; r += 8) dst[(long long)(d0 + r) * N_ + n0 + tx] = t[tx][r];
}

// ---------------------------------------------------------------------------
// small kernels
// ---------------------------------------------------------------------------
__global__ void mlp0_kernel(const float* __restrict__ x, const float* __restrict__ w0,
                            const float* __restrict__ b0, __half* __restrict__ out)
{
    __shared__ float sw[3 * D_];
    __shared__ float sbv[D_];
    for (int i = threadIdx.x; i < 3 * D_; i += blockDim.x) sw[i] = w0[i];
    sbv[threadIdx.x] = b0[threadIdx.x];
    __syncthreads();
    long long m = blockIdx.x;
    int n = threadIdx.x;
    float x0 = x[m * 3 + 0], x1 = x[m * 3 + 1], x2 = x[m * 3 + 2];
    float v = fmaf(x0, sw[n], fmaf(x1, sw[D_ + n], fmaf(x2, sw[2 * D_ + n], sbv[n])));
    out[m * D_ + n] = __float2half_rn(fmaxf(v, 0.f));
}

template<int IN16, int OUT16>
__global__ void ln_kernel(const void* __restrict__ inv, void* __restrict__ outv,
                          const float* __restrict__ gamma, const float* __restrict__ beta)
{
    long long row = blockIdx.x;
    int t = threadIdx.x;
    float v0, v1, v2;
    if (IN16) {
        const __half* p = (const __half*)inv + row * D_;
        v0 = __half2float(p[t]); v1 = __half2float(p[t + 128]); v2 = __half2float(p[t + 256]);
    } else {
        const float* p = (const float*)inv + row * D_;
        v0 = p[t]; v1 = p[t + 128]; v2 = p[t + 256];
    }
    float s = v0 + v1 + v2;
    float sq = v0 * v0 + v1 * v1 + v2 * v2;
    #pragma unroll
    for (int o = 16; o; o >>= 1) {
        s += __shfl_xor_sync(0xffffffffu, s, o);
        sq += __shfl_xor_sync(0xffffffffu, sq, o);
    }
    __shared__ float rs[4], rq[4];
    if ((t & 31) == 0) { rs[t >> 5] = s; rq[t >> 5] = sq; }
    __syncthreads();
    float S = rs[0] + rs[1] + rs[2] + rs[3];
    float Q = rq[0] + rq[1] + rq[2] + rq[3];
    float mean = S * (1.f / (float)D_);
    float var = Q * (1.f / (float)D_) - mean * mean;
    float inv_ = rsqrtf(var + 1e-5f);
    float o0 = (v0 - mean) * inv_ * gamma[t]       + beta[t];
    float o1 = (v1 - mean) * inv_ * gamma[t + 128] + beta[t + 128];
    float o2 = (v2 - mean) * inv_ * gamma[t + 256] + beta[t + 256];
    if (OUT16) {
        __half* q = (__half*)outv + row * D_;
        q[t] = __float2half_rn(o0); q[t + 128] = __float2half_rn(o1); q[t + 256] = __float2half_rn(o2);
    } else {
        float* q = (float*)outv + row * D_;
        q[t] = o0; q[t + 128] = o1; q[t + 256] = o2;
    }
}

__global__ void softmax_kernel(const float* __restrict__ sim, __half* __restrict__ attn)
{
    extern __shared__ float sd[];
    __shared__ float red[8];
    long long row = blockIdx.x;
    const float* p = sim + row * (long long)N_;
    __half* q = attn + row * (long long)N_;
    int t = threadIdx.x;
    float mx = -3.4e38f;
    for (int i = t; i < N_; i += 256) { float v = p[i]; sd[i] = v; mx = fmaxf(mx, v); }
    #pragma unroll
    for (int o = 16; o; o >>= 1) mx = fmaxf(mx, __shfl_xor_sync(0xffffffffu, mx, o));
    if ((t & 31) == 0) red[t >> 5] = mx;
    __syncthreads();
    mx = red[0];
    #pragma unroll
    for (int w = 1; w < 8; w++) mx = fmaxf(mx, red[w]);
    float sum = 0.f;
    for (int i = t; i < N_; i += 256) { float e = __expf(sd[i] - mx); sd[i] = e; sum += e; }
    #pragma unroll
    for (int o = 16; o; o >>= 1) sum += __shfl_xor_sync(0xffffffffu, sum, o);
    __syncthreads();
    if ((t & 31) == 0) red[t >> 5] = sum;
    __syncthreads();
    sum = 0.f;
    #pragma unroll
    for (int w = 0; w < 8; w++) sum += red[w];
    float inv = 1.f / sum;
    for (int i = t; i < N_; i += 256) q[i] = __float2half_rn(sd[i] * inv);
}

__global__ void geglu_kernel(const __half* __restrict__ f1, __half* __restrict__ out)
{
    long long idx = (long long)blockIdx.x * 256 + threadIdx.x;
    long long m = idx / FFH;
    int j = (int)(idx - m * FFH);
    float a = __half2float(f1[m * (2 * FFH) + j]);
    float g = __half2float(f1[m * (2 * FFH) + FFH + j]);
    float ge = 0.5f * g * (1.f + erff(g * 0.70710678118654752440f));
    out[idx] = __float2half_rn(a * ge);
}

// ---------------------------------------------------------------------------
// Launch
// ---------------------------------------------------------------------------
extern "C" void kernel_launch(void* const* d_in, const int* in_sizes, int n_in,
                              void* d_out, int out_size)
{
    const float* x        = (const float*)d_in[0];
    const float* mlp_w0   = (const float*)d_in[1];
    const float* mlp_b0   = (const float*)d_in[2];
    const float* mlp_w1   = (const float*)d_in[3];
    const float* mlp_b1   = (const float*)d_in[4];
    const float* mlp_w2   = (const float*)d_in[5];
    const float* mlp_b2   = (const float*)d_in[6];
    const float* mlp_w3   = (const float*)d_in[7];
    const float* mlp_b3   = (const float*)d_in[8];
    const float* query    = (const float*)d_in[9];
    const float* ln_q_g   = (const float*)d_in[10];
    const float* ln_q_b   = (const float*)d_in[11];
    const float* ln_ctx_g = (const float*)d_in[12];
    const float* ln_ctx_b = (const float*)d_in[13];
    const float* wq       = (const float*)d_in[14];
    const float* wkv      = (const float*)d_in[15];
    const float* wo       = (const float*)d_in[16];
    const float* bo       = (const float*)d_in[17];
    const float* ln_ff_g  = (const float*)d_in[18];
    const float* ln_ff_b  = (const float*)d_in[19];
    const float* ff_w1    = (const float*)d_in[20];
    const float* ff_b1    = (const float*)d_in[21];
    const float* ff_w2    = (const float*)d_in[22];
    const float* ff_b2    = (const float*)d_in[23];

    static __half *hA = 0, *hB = 0, *kv16 = 0, *attn16 = 0, *qn16 = 0, *q16 = 0,
                  *av16 = 0, *fn16 = 0, *f116 = 0, *gg16 = 0, *wh = 0;
    static float *sim = 0, *x1 = 0;
    if (!hA) {
        cudaGetSymbolAddress((void**)&hA, g_h16a);
        cudaGetSymbolAddress((void**)&hB, g_h16b);
        cudaGetSymbolAddress((void**)&kv16, g_kv16);
        cudaGetSymbolAddress((void**)&attn16, g_attn16);
        cudaGetSymbolAddress((void**)&qn16, g_qn16);
        cudaGetSymbolAddress((void**)&q16, g_q16);
        cudaGetSymbolAddress((void**)&av16, g_av16);
        cudaGetSymbolAddress((void**)&fn16, g_fn16);
        cudaGetSymbolAddress((void**)&f116, g_f116);
        cudaGetSymbolAddress((void**)&gg16, g_gg16);
        cudaGetSymbolAddress((void**)&wh, g_wh);
        cudaGetSymbolAddress((void**)&sim, g_sim);
        cudaGetSymbolAddress((void**)&x1, g_x1);
        cudaFuncSetAttribute(gemm_h<0>, cudaFuncAttributeMaxDynamicSharedMemorySize, SMEM_BYTES);
        cudaFuncSetAttribute(gemm_h<1>, cudaFuncAttributeMaxDynamicSharedMemorySize, SMEM_BYTES);
    }
    __half* vt = hB;  // reuse after ctx is consumed

    dim3 tb(32, 8);
    wcvt<<<dim3(12, 12), tb>>>(mlp_w1, D_, D_, wh + W1OFF);
    wcvt<<<dim3(12, 12), tb>>>(mlp_w2, D_, D_, wh + W2OFF);
    wcvt<<<dim3(12, 12), tb>>>(mlp_w3, D_, D_, wh + W3OFF);
    wcvt<<<dim3(12, 12), tb>>>(wq, D_, D_, wh + WQOFF);
    wcvt<<<dim3(24, 12), tb>>>(wkv, D_, 2 * D_, wh + WKVOFF);
    wcvt<<<dim3(12, 12), tb>>>(wo, D_, D_, wh + WOOFF);
    wcvt<<<dim3(96, 12), tb>>>(ff_w1, D_, 2 * FFH, wh + FF1OFF);
    wcvt<<<dim3(12, 48), tb>>>(ff_w2, FFH, D_, wh + FF2OFF);

    // point MLP
    mlp0_kernel<<<MCTX, D_>>>(x, mlp_w0, mlp_b0, hA);
    gemm_h<1><<<dim3(3, MCTX / 128), 256, SMEM_BYTES>>>(
        hA, D_, 0, wh + W1OFF, D_, 0, hB, D_, 0, D_, mlp_b1, 1, 0, 0, 0, 1.f);
    gemm_h<1><<<dim3(3, MCTX / 128), 256, SMEM_BYTES>>>(
        hB, D_, 0, wh + W2OFF, D_, 0, hA, D_, 0, D_, mlp_b2, 1, 0, 0, 0, 1.f);
    gemm_h<1><<<dim3(3, MCTX / 128), 256, SMEM_BYTES>>>(
        hA, D_, 0, wh + W3OFF, D_, 0, hB, D_, 0, D_, mlp_b3, 0, 0, 0, 0, 1.f);

    // LN(ctx) -> cn (hA); KV projection
    ln_kernel<1, 1><<<MCTX, 128>>>(hB, hA, ln_ctx_g, ln_ctx_b);
    gemm_h<1><<<dim3(6, MCTX / 128), 256, SMEM_BYTES>>>(
        hA, D_, 0, wh + WKVOFF, D_, 0, kv16, 2 * D_, 0, D_, 0, 0, 0, 0, 0, 1.f);
    vtrans<<<dim3(N_ / 32, D_ / 32, B_), tb>>>(kv16, vt);

    // Q path
    ln_kernel<0, 1><<<L_, 128>>>(query, qn16, ln_q_g, ln_q_b);
    gemm_h<1><<<dim3(3, L_ / 128), 256, SMEM_BYTES>>>(
        qn16, D_, 0, wh + WQOFF, D_, 0, q16, D_, 0, D_, 0, 0, 0, 0, 0, 1.f);

    // sim = Q @ K^T * scale (fp32 out)
    gemm_h<0><<<dim3(N_ / 128, L_ / 128, B_), 256, SMEM_BYTES>>>(
        q16, D_, 0, kv16, 2 * D_, (long long)N_ * 2 * D_,
        sim, N_, (long long)L_ * N_, D_, 0, 0, 0, 0, 0, 0.05103103630798288f);
    softmax_kernel<<<B_ * L_, 256, N_ * sizeof(float)>>>(sim, attn16);

    // out = attn @ V
    gemm_h<1><<<dim3(D_ / 128, L_ / 128, B_), 256, SMEM_BYTES>>>(
        attn16, N_, (long long)L_ * N_, vt, N_, (long long)D_ * N_,
        av16, D_, (long long)L_ * D_, N_, 0, 0, 0, 0, 0, 1.f);

    // x1 = out @ wo + bo + broadcast(query)  (fp32)
    gemm_h<0><<<dim3(3, B_ * L_ / 128), 256, SMEM_BYTES>>>(
        av16, D_, 0, wh + WOOFF, D_, 0, x1, D_, 0, D_, bo, 0, query, L_, D_, 1.f);

    // feedforward
    ln_kernel<0, 1><<<B_ * L_, 128>>>(x1, fn16, ln_ff_g, ln_ff_b);
    gemm_h<1><<<dim3(24, B_ * L_ / 128), 256, SMEM_BYTES>>>(
        fn16, D_, 0, wh + FF1OFF, D_, 0, f116, 2 * FFH, 0, D_, ff_b1, 0, 0, 0, 0, 1.f);
    geglu_kernel<<<(B_ * L_ * FFH) / 256, 256>>>(f116, gg16);
    gemm_h<0><<<dim3(3, B_ * L_ / 128), 256, SMEM_BYTES>>>(
        gg16, FFH, 0, wh + FF2OFF, FFH, 0, (float*)d_out, D_, 0, FFH,
        ff_b2, 0, x1, 0, D_, 1.f);
}

// round 8
// speedup vs baseline: 3.8219x; 1.0034x over previous
#include <cuda_runtime.h>
#include <cuda_fp16.h>
#include <math.h>
#include <stdint.h>

#define B_  16
#define N_  8192
#define L_  512
#define D_  384
#define FFH 1536
#define MCTX (B_ * N_)

// ---------------------------------------------------------------------------
// Scratch
// ---------------------------------------------------------------------------
__device__ __half g_h16a[MCTX * D_];
__device__ __half g_h16b[MCTX * D_];            // ctx, later reused as V^T
__device__ __half g_kv16[MCTX * 2 * D_];
__device__ float  g_sim[(long long)B_ * L_ * N_];
__device__ __half g_attn16[(long long)B_ * L_ * N_];
__device__ __half g_qn16[L_ * D_];
__device__ __half g_q16[L_ * D_];
__device__ __half g_av16[B_ * L_ * D_];
__device__ float  g_x1[B_ * L_ * D_];
__device__ __half g_fn16[B_ * L_ * D_];
__device__ __half g_gg16[B_ * L_ * FFH];

// fp16 weights, transposed to [N,K]
#define W1OFF   0
#define W2OFF   147456
#define W3OFF   294912
#define WQOFF   442368
#define WKVOFF  589824
#define WOOFF   884736
#define FF1OFF  1032192
#define FF2OFF  2211840
#define WTOT    2801664
__device__ __half g_wh[WTOT];

// ---------------------------------------------------------------------------
// helpers
// ---------------------------------------------------------------------------
__device__ __forceinline__ uint32_t smem_u32(const void* p) {
    uint32_t a;
    asm("{ .reg .u64 t; cvta.to.shared.u64 t, %1; cvt.u32.u64 %0, t; }" : "=r"(a) : "l"(p));
    return a;
}
__device__ __forceinline__ void ldsm4(uint32_t* r, uint32_t addr) {
    asm volatile("ldmatrix.sync.aligned.m8n8.x4.shared.b16 {%0,%1,%2,%3}, [%4];"
        : "=r"(r[0]), "=r"(r[1]), "=r"(r[2]), "=r"(r[3]) : "r"(addr));
}
__device__ __forceinline__ void mma16816(float* c, const uint32_t* a, const uint32_t* b) {
    asm volatile("mma.sync.aligned.m16n8k16.row.col.f32.f16.f16.f32 "
        "{%0,%1,%2,%3}, {%4,%5,%6,%7}, {%8,%9}, {%0,%1,%2,%3};"
        : "+f"(c[0]), "+f"(c[1]), "+f"(c[2]), "+f"(c[3])
        : "r"(a[0]), "r"(a[1]), "r"(a[2]), "r"(a[3]), "r"(b[0]), "r"(b[1]));
}
#define CPA16(dst, src) \
    asm volatile("cp.async.cg.shared.global [%0], [%1], 16;" :: "r"(dst), "l"(src))
#define CP_COMMIT() asm volatile("cp.async.commit_group;" ::: "memory")
#define CP_WAIT2()  asm volatile("cp.async.wait_group 2;" ::: "memory")

// ===========================================================================
// GEMM (R4-validated): smem 4 stages x 16KB, 8x8 block layout
// off(row,k) = (row>>3)*512 + (k>>3)*128 + (row&7)*16 + (k&7)*2
// ===========================================================================
#define STAGE_BYTES 16384
#define SMEM_BYTES  65536

// EPI: 0 = fp32 out, 1 = fp16 out, 2 = GEGLU fp16 out (interleaved a/g cols)
template<int EPI>
__global__ void __launch_bounds__(256)
gemm_h(const __half* __restrict__ A, int lda, long long sA,
       const __half* __restrict__ B, int ldb, long long sB,
       void* __restrict__ Cv, int ldc, long long sC,
       int K, const float* __restrict__ bias, int relu,
       const float* __restrict__ res, int res_mod, int res_ld, float scale)
{
    extern __shared__ __align__(1024) char smem[];
    const int tid = threadIdx.x, lane = tid & 31, warp = tid >> 5;
    A += blockIdx.z * sA;
    B += blockIdx.z * sB;
    const int m0 = blockIdx.y * 128, n0 = blockIdx.x * 128;
    const int wm0 = (warp >> 1) * 32, wn0 = (warp & 1) * 64;
    uint32_t sb = smem_u32(smem);

    const int v0 = tid, v1 = tid + 256;
    const int rA0 = v0 >> 2, kb0 = v0 & 3;
    const int rA1 = v1 >> 2, kb1 = v1 & 3;
    const uint32_t dA0 = (rA0 >> 3) * 512 + kb0 * 128 + (rA0 & 7) * 16;
    const uint32_t dA1 = (rA1 >> 3) * 512 + kb1 * 128 + (rA1 & 7) * 16;
    const __half* pA0 = A + (long long)(m0 + rA0) * lda + kb0 * 8;
    const __half* pA1 = A + (long long)(m0 + rA1) * lda + kb1 * 8;
    const __half* pB0 = B + (long long)(n0 + rA0) * ldb + kb0 * 8;
    const __half* pB1 = B + (long long)(n0 + rA1) * ldb + kb1 * 8;

    const int rA = wm0 + (lane & 15);
    const uint32_t offA0 = (rA >> 3) * 512 + (rA & 7) * 16 + (lane >> 4) * 128;
    const int nB = wn0 + (lane >> 4) * 8 + (lane & 7);
    const uint32_t offB0 = (nB >> 3) * 512 + (nB & 7) * 16 + ((lane >> 3) & 1) * 128;

    float acc[2][8][4];
    #pragma unroll
    for (int i = 0; i < 2; i++)
        #pragma unroll
        for (int j = 0; j < 8; j++)
            #pragma unroll
            for (int q = 0; q < 4; q++) acc[i][j][q] = 0.f;

    const int KC = K >> 5;

#define ISSUE(kc) do {                                                          \
    uint32_t st = sb + ((kc) & 3) * STAGE_BYTES;                                \
    long long ko = (long long)(kc) * 32;                                        \
    CPA16(st + dA0, pA0 + ko);                                                  \
    CPA16(st + dA1, pA1 + ko);                                                  \
    CPA16(st + 8192 + dA0, pB0 + ko);                                           \
    CPA16(st + 8192 + dA1, pB1 + ko);                                           \
} while (0)

    ISSUE(0); CP_COMMIT();
    ISSUE(1); CP_COMMIT();
    ISSUE(2); CP_COMMIT();

    for (int kc = 0; kc < KC; kc++) {
        CP_WAIT2();
        __syncthreads();
        if (kc + 3 < KC) ISSUE(kc + 3);
        CP_COMMIT();

        uint32_t st = sb + (kc & 3) * STAGE_BYTES;
        #pragma unroll
        for (int s = 0; s < 2; s++) {
            uint32_t base = st + s * 256;
            uint32_t ah[2][4], b[4];
            ldsm4(ah[0], base + offA0);
            ldsm4(ah[1], base + offA0 + 1024);
            #pragma unroll
            for (int p = 0; p < 4; p++) {
                ldsm4(b, base + 8192 + offB0 + p * 1024);
                mma16816(acc[0][2 * p],     ah[0], b);
                mma16816(acc[0][2 * p + 1], ah[0], b + 2);
                mma16816(acc[1][2 * p],     ah[1], b);
                mma16816(acc[1][2 * p + 1], ah[1], b + 2);
            }
        }
        __syncthreads();
    }

    #pragma unroll
    for (int mt = 0; mt < 2; mt++) {
        #pragma unroll
        for (int nt = 0; nt < 8; nt++) {
            int rr = m0 + wm0 + mt * 16 + (lane >> 2);
            int cc = n0 + wn0 + nt * 8 + (lane & 3) * 2;
            float b0, b1;
            if (EPI == 2) { b0 = bias[cc >> 1]; b1 = bias[FFH + (cc >> 1)]; }
            else { b0 = bias ? bias[cc] : 0.f; b1 = bias ? bias[cc + 1] : 0.f; }
            #pragma unroll
            for (int h = 0; h < 2; h++) {
                int rrow = rr + h * 8;
                float w0 = acc[mt][nt][2 * h + 0] * scale + b0;
                float w1 = acc[mt][nt][2 * h + 1] * scale + b1;
                if (EPI == 2) {
                    float ge = 0.5f * w1 * (1.f + erff(w1 * 0.70710678118654752440f));
                    ((__half*)Cv)[blockIdx.z * sC + (long long)rrow * ldc + (cc >> 1)] =
                        __float2half_rn(w0 * ge);
                } else {
                    if (relu) { w0 = fmaxf(w0, 0.f); w1 = fmaxf(w1, 0.f); }
                    if (res) {
                        const float* rp = res + (long long)(res_mod ? (rrow % res_mod) : rrow) * res_ld + cc;
                        w0 += rp[0]; w1 += rp[1];
                    }
                    if (EPI == 1)
                        *(__half2*)((__half*)Cv + blockIdx.z * sC + (long long)rrow * ldc + cc) =
                            __floats2half2_rn(w0, w1);
                    else
                        *(float2*)((float*)Cv + blockIdx.z * sC + (long long)rrow * ldc + cc) =
                            make_float2(w0, w1);
                }
            }
        }
    }
#undef ISSUE
}

// ---------------------------------------------------------------------------
// weight prep
// ---------------------------------------------------------------------------
__global__ void wcvt(const float* __restrict__ W, int K, int N, __half* __restrict__ out)
{
    __shared__ float t[32][33];
    int n0 = blockIdx.x * 32, k0 = blockIdx.y * 32;
    int tx = threadIdx.x, ty = threadIdx.y;
    for (int r = ty; r < 32; r += 8) t[r][tx] = W[(long long)(k0 + r) * N + n0 + tx];
    __syncthreads();
    for (int r = ty; r < 32; r += 8)
        out[(long long)(n0 + r) * K + k0 + tx] = __float2half_rn(t[tx][r]);
}

// ff_w1 [384, 3072] -> interleaved transposed [3072, 384]: row n' = 2*(n%1536) + n/1536
__global__ void wcvt_ff1(const float* __restrict__ W, __half* __restrict__ out)
{
    __shared__ float t[32][33];
    int n0 = blockIdx.x * 32, k0 = blockIdx.y * 32;
    int tx = threadIdx.x, ty = threadIdx.y;
    for (int r = ty; r < 32; r += 8) t[r][tx] = W[(long long)(k0 + r) * (2 * FFH) + n0 + tx];
    __syncthreads();
    for (int r = ty; r < 32; r += 8) {
        int n = n0 + r;
        int np = (n < FFH) ? 2 * n : 2 * (n - FFH) + 1;
        out[(long long)np * D_ + k0 + tx] = __float2half_rn(t[tx][r]);
    }
}

// V transpose fp16: kv16[B*N,768] cols 384..767 -> vt[B,384,8192]
__global__ void vtrans(const __half* __restrict__ kv, __half* __restrict__ vt)
{
    __shared__ __half t[32][34];
    int n0 = blockIdx.x * 32, d0 = blockIdx.y * 32, b = blockIdx.z;
    int tx = threadIdx.x, ty = threadIdx.y;
    const __half* src = kv + (long long)b * N_ * 768 + D_;
    for (int r = ty; r < 32; r += 8) t[r][tx] = src[(long long)(n0 + r) * 768 + d0 + tx];
    __syncthreads();
    __half* dst = vt + (long long)b * D_ * N_;
    for (int r = ty; r < 32; r += 8) dst[(long long)(d0 + r) * N_ + n0 + tx] = t[tx][r];
}

// ---------------------------------------------------------------------------
// small kernels
// ---------------------------------------------------------------------------
__global__ void mlp0_kernel(const float* __restrict__ x, const float* __restrict__ w0,
                            const float* __restrict__ b0, __half* __restrict__ out)
{
    __shared__ float sw[3 * D_];
    __shared__ float sbv[D_];
    for (int i = threadIdx.x; i < 3 * D_; i += blockDim.x) sw[i] = w0[i];
    sbv[threadIdx.x] = b0[threadIdx.x];
    __syncthreads();
    long long m = blockIdx.x;
    int n = threadIdx.x;
    float x0 = x[m * 3 + 0], x1 = x[m * 3 + 1], x2 = x[m * 3 + 2];
    float v = fmaf(x0, sw[n], fmaf(x1, sw[D_ + n], fmaf(x2, sw[2 * D_ + n], sbv[n])));
    out[m * D_ + n] = __float2half_rn(fmaxf(v, 0.f));
}

template<int IN16>
__global__ void ln_kernel(const void* __restrict__ inv, __half* __restrict__ outp,
                          const float* __restrict__ gamma, const float* __restrict__ beta)
{
    long long row = blockIdx.x;
    int t = threadIdx.x;
    float v0, v1, v2;
    if (IN16) {
        const __half* p = (const __half*)inv + row * D_;
        v0 = __half2float(p[t]); v1 = __half2float(p[t + 128]); v2 = __half2float(p[t + 256]);
    } else {
        const float* p = (const float*)inv + row * D_;
        v0 = p[t]; v1 = p[t + 128]; v2 = p[t + 256];
    }
    float s = v0 + v1 + v2;
    float sq = v0 * v0 + v1 * v1 + v2 * v2;
    #pragma unroll
    for (int o = 16; o; o >>= 1) {
        s += __shfl_xor_sync(0xffffffffu, s, o);
        sq += __shfl_xor_sync(0xffffffffu, sq, o);
    }
    __shared__ float rs[4], rq[4];
    if ((t & 31) == 0) { rs[t >> 5] = s; rq[t >> 5] = sq; }
    __syncthreads();
    float S = rs[0] + rs[1] + rs[2] + rs[3];
    float Q = rq[0] + rq[1] + rq[2] + rq[3];
    float mean = S * (1.f / (float)D_);
    float var = Q * (1.f / (float)D_) - mean * mean;
    float inv_ = rsqrtf(var + 1e-5f);
    __half* q = outp + row * D_;
    q[t]       = __float2half_rn((v0 - mean) * inv_ * gamma[t]       + beta[t]);
    q[t + 128] = __float2half_rn((v1 - mean) * inv_ * gamma[t + 128] + beta[t + 128]);
    q[t + 256] = __float2half_rn((v2 - mean) * inv_ * gamma[t + 256] + beta[t + 256]);
}

__global__ void softmax_kernel(const float* __restrict__ sim, __half* __restrict__ attn)
{
    extern __shared__ float sd[];
    __shared__ float red[8];
    long long row = blockIdx.x;
    const float* p = sim + row * (long long)N_;
    __half* q = attn + row * (long long)N_;
    int t = threadIdx.x;
    float mx = -3.4e38f;
    for (int i = t; i < N_; i += 256) { float v = p[i]; sd[i] = v; mx = fmaxf(mx, v); }
    #pragma unroll
    for (int o = 16; o; o >>= 1) mx = fmaxf(mx, __shfl_xor_sync(0xffffffffu, mx, o));
    if ((t & 31) == 0) red[t >> 5] = mx;
    __syncthreads();
    mx = red[0];
    #pragma unroll
    for (int w = 1; w < 8; w++) mx = fmaxf(mx, red[w]);
    float sum = 0.f;
    for (int i = t; i < N_; i += 256) { float e = __expf(sd[i] - mx); sd[i] = e; sum += e; }
    #pragma unroll
    for (int o = 16; o; o >>= 1) sum += __shfl_xor_sync(0xffffffffu, sum, o);
    __syncthreads();
    if ((t & 31) == 0) red[t >> 5] = sum;
    __syncthreads();
    sum = 0.f;
    #pragma unroll
    for (int w = 0; w < 8; w++) sum += red[w];
    float inv = 1.f / sum;
    for (int i = t; i < N_; i += 256) q[i] = __float2half_rn(sd[i] * inv);
}

// ---------------------------------------------------------------------------
// Launch
// ---------------------------------------------------------------------------
extern "C" void kernel_launch(void* const* d_in, const int* in_sizes, int n_in,
                              void* d_out, int out_size)
{
    const float* x        = (const float*)d_in[0];
    const float* mlp_w0   = (const float*)d_in[1];
    const float* mlp_b0   = (const float*)d_in[2];
    const float* mlp_w1   = (const float*)d_in[3];
    const float* mlp_b1   = (const float*)d_in[4];
    const float* mlp_w2   = (const float*)d_in[5];
    const float* mlp_b2   = (const float*)d_in[6];
    const float* mlp_w3   = (const float*)d_in[7];
    const float* mlp_b3   = (const float*)d_in[8];
    const float* query    = (const float*)d_in[9];
    const float* ln_q_g   = (const float*)d_in[10];
    const float* ln_q_b   = (const float*)d_in[11];
    const float* ln_ctx_g = (const float*)d_in[12];
    const float* ln_ctx_b = (const float*)d_in[13];
    const float* wq       = (const float*)d_in[14];
    const float* wkv      = (const float*)d_in[15];
    const float* wo       = (const float*)d_in[16];
    const float* bo       = (const float*)d_in[17];
    const float* ln_ff_g  = (const float*)d_in[18];
    const float* ln_ff_b  = (const float*)d_in[19];
    const float* ff_w1    = (const float*)d_in[20];
    const float* ff_b1    = (const float*)d_in[21];
    const float* ff_w2    = (const float*)d_in[22];
    const float* ff_b2    = (const float*)d_in[23];

    static __half *hA = 0, *hB = 0, *kv16 = 0, *attn16 = 0, *qn16 = 0, *q16 = 0,
                  *av16 = 0, *fn16 = 0, *gg16 = 0, *wh = 0;
    static float *sim = 0, *x1 = 0;
    if (!hA) {
        cudaGetSymbolAddress((void**)&hA, g_h16a);
        cudaGetSymbolAddress((void**)&hB, g_h16b);
        cudaGetSymbolAddress((void**)&kv16, g_kv16);
        cudaGetSymbolAddress((void**)&attn16, g_attn16);
        cudaGetSymbolAddress((void**)&qn16, g_qn16);
        cudaGetSymbolAddress((void**)&q16, g_q16);
        cudaGetSymbolAddress((void**)&av16, g_av16);
        cudaGetSymbolAddress((void**)&fn16, g_fn16);
        cudaGetSymbolAddress((void**)&gg16, g_gg16);
        cudaGetSymbolAddress((void**)&wh, g_wh);
        cudaGetSymbolAddress((void**)&sim, g_sim);
        cudaGetSymbolAddress((void**)&x1, g_x1);
        cudaFuncSetAttribute(gemm_h<0>, cudaFuncAttributeMaxDynamicSharedMemorySize, SMEM_BYTES);
        cudaFuncSetAttribute(gemm_h<1>, cudaFuncAttributeMaxDynamicSharedMemorySize, SMEM_BYTES);
        cudaFuncSetAttribute(gemm_h<2>, cudaFuncAttributeMaxDynamicSharedMemorySize, SMEM_BYTES);
    }
    __half* vt = hB;  // reuse after ctx consumed

    dim3 tb(32, 8);
    wcvt<<<dim3(12, 12), tb>>>(mlp_w1, D_, D_, wh + W1OFF);
    wcvt<<<dim3(12, 12), tb>>>(mlp_w2, D_, D_, wh + W2OFF);
    wcvt<<<dim3(12, 12), tb>>>(mlp_w3, D_, D_, wh + W3OFF);
    wcvt<<<dim3(12, 12), tb>>>(wq, D_, D_, wh + WQOFF);
    wcvt<<<dim3(24, 12), tb>>>(wkv, D_, 2 * D_, wh + WKVOFF);
    wcvt<<<dim3(12, 12), tb>>>(wo, D_, D_, wh + WOOFF);
    wcvt_ff1<<<dim3(96, 12), tb>>>(ff_w1, wh + FF1OFF);
    wcvt<<<dim3(12, 48), tb>>>(ff_w2, FFH, D_, wh + FF2OFF);

    // point MLP
    mlp0_kernel<<<MCTX, D_>>>(x, mlp_w0, mlp_b0, hA);
    gemm_h<1><<<dim3(3, MCTX / 128), 256, SMEM_BYTES>>>(
        hA, D_, 0, wh + W1OFF, D_, 0, hB, D_, 0, D_, mlp_b1, 1, 0, 0, 0, 1.f);
    gemm_h<1><<<dim3(3, MCTX / 128), 256, SMEM_BYTES>>>(
        hB, D_, 0, wh + W2OFF, D_, 0, hA, D_, 0, D_, mlp_b2, 1, 0, 0, 0, 1.f);
    gemm_h<1><<<dim3(3, MCTX / 128), 256, SMEM_BYTES>>>(
        hA, D_, 0, wh + W3OFF, D_, 0, hB, D_, 0, D_, mlp_b3, 0, 0, 0, 0, 1.f);

    // LN(ctx) -> hA; KV projection
    ln_kernel<1><<<MCTX, 128>>>(hB, hA, ln_ctx_g, ln_ctx_b);
    gemm_h<1><<<dim3(6, MCTX / 128), 256, SMEM_BYTES>>>(
        hA, D_, 0, wh + WKVOFF, D_, 0, kv16, 2 * D_, 0, D_, 0, 0, 0, 0, 0, 1.f);
    vtrans<<<dim3(N_ / 32, D_ / 32, B_), tb>>>(kv16, vt);

    // Q path (1/sqrt(D) folded into wq GEMM)
    ln_kernel<0><<<L_, 128>>>(query, qn16, ln_q_g, ln_q_b);
    gemm_h<1><<<dim3(3, L_ / 128), 256, SMEM_BYTES>>>(
        qn16, D_, 0, wh + WQOFF, D_, 0, q16, D_, 0, D_, 0, 0, 0, 0, 0,
        0.05103103630798288f);

    // sim = Q @ K^T (fp32 out; scale already in Q)
    gemm_h<0><<<dim3(N_ / 128, L_ / 128, B_), 256, SMEM_BYTES>>>(
        q16, D_, 0, kv16, 2 * D_, (long long)N_ * 2 * D_,
        sim, N_, (long long)L_ * N_, D_, 0, 0, 0, 0, 0, 1.f);
    softmax_kernel<<<B_ * L_, 256, N_ * sizeof(float)>>>(sim, attn16);

    // out = attn @ V
    gemm_h<1><<<dim3(D_ / 128, L_ / 128, B_), 256, SMEM_BYTES>>>(
        attn16, N_, (long long)L_ * N_, vt, N_, (long long)D_ * N_,
        av16, D_, (long long)L_ * D_, N_, 0, 0, 0, 0, 0, 1.f);

    // x1 = av @ wo + bo + broadcast(query)
    gemm_h<0><<<dim3(3, B_ * L_ / 128), 256, SMEM_BYTES>>>(
        av16, D_, 0, wh + WOOFF, D_, 0, x1, D_, 0, D_, bo, 0, query, L_, D_, 1.f);

    // feedforward: LN -> ff1+GEGLU fused -> ff2
    ln_kernel<0><<<B_ * L_, 128>>>(x1, fn16, ln_ff_g, ln_ff_b);
    gemm_h<2><<<dim3(24, B_ * L_ / 128), 256, SMEM_BYTES>>>(
        fn16, D_, 0, wh + FF1OFF, D_, 0, gg16, FFH, 0, D_, ff_b1, 0, 0, 0, 0, 1.f);
    gemm_h<0><<<dim3(3, B_ * L_ / 128), 256, SMEM_BYTES>>>(
        gg16, FFH, 0, wh + FF2OFF, FFH, 0, (float*)d_out, D_, 0, FFH,
        ff_b2, 0, x1, 0, D_, 1.f);
}

// round 9
// speedup vs baseline: 3.9253x; 1.0270x over previous
#include <cuda_runtime.h>
#include <cuda_fp16.h>
#include <math.h>
#include <stdint.h>

#define B_  16
#define N_  8192
#define L_  512
#define D_  384
#define FFH 1536
#define MCTX (B_ * N_)

// ---------------------------------------------------------------------------
// Scratch
// ---------------------------------------------------------------------------
__device__ __half g_h16a[MCTX * D_];
__device__ __half g_h16b[MCTX * D_];            // ctx, later reused as V^T
__device__ __half g_kv16[MCTX * 2 * D_];
__device__ float  g_sim[(long long)B_ * L_ * N_];   // also split-K partials
__device__ __half g_attn16[(long long)B_ * L_ * N_];
__device__ __half g_qn16[L_ * D_];
__device__ __half g_q16[L_ * D_];
__device__ __half g_av16[B_ * L_ * D_];
__device__ float  g_x1[B_ * L_ * D_];
__device__ __half g_fn16[B_ * L_ * D_];
__device__ __half g_gg16[B_ * L_ * FFH];

// fp16 weights, transposed to [N,K]
#define W1OFF   0
#define W2OFF   147456
#define W3OFF   294912
#define WQOFF   442368
#define WKVOFF  589824
#define WOOFF   884736
#define FF1OFF  1032192
#define FF2OFF  2211840
#define WTOT    2801664
__device__ __half g_wh[WTOT];

// ---------------------------------------------------------------------------
// helpers
// ---------------------------------------------------------------------------
__device__ __forceinline__ uint32_t smem_u32(const void* p) {
    uint32_t a;
    asm("{ .reg .u64 t; cvta.to.shared.u64 t, %1; cvt.u32.u64 %0, t; }" : "=r"(a) : "l"(p));
    return a;
}
__device__ __forceinline__ void ldsm4(uint32_t* r, uint32_t addr) {
    asm volatile("ldmatrix.sync.aligned.m8n8.x4.shared.b16 {%0,%1,%2,%3}, [%4];"
        : "=r"(r[0]), "=r"(r[1]), "=r"(r[2]), "=r"(r[3]) : "r"(addr));
}
__device__ __forceinline__ void mma16816(float* c, const uint32_t* a, const uint32_t* b) {
    asm volatile("mma.sync.aligned.m16n8k16.row.col.f32.f16.f16.f32 "
        "{%0,%1,%2,%3}, {%4,%5,%6,%7}, {%8,%9}, {%0,%1,%2,%3};"
        : "+f"(c[0]), "+f"(c[1]), "+f"(c[2]), "+f"(c[3])
        : "r"(a[0]), "r"(a[1]), "r"(a[2]), "r"(a[3]), "r"(b[0]), "r"(b[1]));
}
#define CPA16(dst, src) \
    asm volatile("cp.async.cg.shared.global [%0], [%1], 16;" :: "r"(dst), "l"(src))
#define CP_COMMIT() asm volatile("cp.async.commit_group;" ::: "memory")
#define CP_WAIT2()  asm volatile("cp.async.wait_group 2;" ::: "memory")

// ===========================================================================
// GEMM (R4-validated layout): smem 4 stages x 16KB, 8x8 block layout
// off(row,k) = (row>>3)*512 + (k>>3)*128 + (row&7)*16 + (k&7)*2
// ===========================================================================
#define STAGE_BYTES 16384
#define SMEM_BYTES  65536

// EPI: 0 = fp32 out, 1 = fp16 out, 2 = GEGLU fp16 out (interleaved a/g cols)
// SPLITK: 0 = normal (z = batch); >0 = K-chunk size, z = split*16 + batch
template<int EPI, int SPLITK>
__global__ void __launch_bounds__(256, 2)
gemm_h(const __half* __restrict__ A, int lda, long long sA,
       const __half* __restrict__ B, int ldb, long long sB,
       void* __restrict__ Cv, int ldc, long long sC,
       int K, const float* __restrict__ bias, int relu,
       const float* __restrict__ res, int res_mod, int res_ld, float scale)
{
    extern __shared__ __align__(1024) char smem[];
    const int tid = threadIdx.x, lane = tid & 31, warp = tid >> 5;
    if (SPLITK) {
        int s = blockIdx.z >> 4, b = blockIdx.z & 15;
        A += (long long)b * sA + s * SPLITK;
        B += (long long)b * sB + s * SPLITK;
    } else {
        A += blockIdx.z * sA;
        B += blockIdx.z * sB;
    }
    const int m0 = blockIdx.y * 128, n0 = blockIdx.x * 128;
    const int wm0 = (warp >> 1) * 32, wn0 = (warp & 1) * 64;
    uint32_t sb = smem_u32(smem);

    const int v0 = tid, v1 = tid + 256;
    const int rA0 = v0 >> 2, kb0 = v0 & 3;
    const int rA1 = v1 >> 2, kb1 = v1 & 3;
    const uint32_t dA0 = (rA0 >> 3) * 512 + kb0 * 128 + (rA0 & 7) * 16;
    const uint32_t dA1 = (rA1 >> 3) * 512 + kb1 * 128 + (rA1 & 7) * 16;
    const __half* pA0 = A + (long long)(m0 + rA0) * lda + kb0 * 8;
    const __half* pA1 = A + (long long)(m0 + rA1) * lda + kb1 * 8;
    const __half* pB0 = B + (long long)(n0 + rA0) * ldb + kb0 * 8;
    const __half* pB1 = B + (long long)(n0 + rA1) * ldb + kb1 * 8;

    const int rA = wm0 + (lane & 15);
    const uint32_t offA0 = (rA >> 3) * 512 + (rA & 7) * 16 + (lane >> 4) * 128;
    const int nB = wn0 + (lane >> 4) * 8 + (lane & 7);
    const uint32_t offB0 = (nB >> 3) * 512 + (nB & 7) * 16 + ((lane >> 3) & 1) * 128;

    float acc[2][8][4];
    #pragma unroll
    for (int i = 0; i < 2; i++)
        #pragma unroll
        for (int j = 0; j < 8; j++)
            #pragma unroll
            for (int q = 0; q < 4; q++) acc[i][j][q] = 0.f;

    const int KC = K >> 5;

#define ISSUE(kc) do {                                                          \
    uint32_t st = sb + ((kc) & 3) * STAGE_BYTES;                                \
    long long ko = (long long)(kc) * 32;                                        \
    CPA16(st + dA0, pA0 + ko);                                                  \
    CPA16(st + dA1, pA1 + ko);                                                  \
    CPA16(st + 8192 + dA0, pB0 + ko);                                           \
    CPA16(st + 8192 + dA1, pB1 + ko);                                           \
} while (0)

    ISSUE(0); CP_COMMIT();
    ISSUE(1); CP_COMMIT();
    ISSUE(2); CP_COMMIT();

    for (int kc = 0; kc < KC; kc++) {
        CP_WAIT2();
        __syncthreads();
        if (kc + 3 < KC) ISSUE(kc + 3);
        CP_COMMIT();

        uint32_t st = sb + (kc & 3) * STAGE_BYTES;
        #pragma unroll
        for (int s = 0; s < 2; s++) {
            uint32_t base = st + s * 256;
            uint32_t ah[2][4], b[4];
            ldsm4(ah[0], base + offA0);
            ldsm4(ah[1], base + offA0 + 1024);
            #pragma unroll
            for (int p = 0; p < 4; p++) {
                ldsm4(b, base + 8192 + offB0 + p * 1024);
                mma16816(acc[0][2 * p],     ah[0], b);
                mma16816(acc[0][2 * p + 1], ah[0], b + 2);
                mma16816(acc[1][2 * p],     ah[1], b);
                mma16816(acc[1][2 * p + 1], ah[1], b + 2);
            }
        }
        __syncthreads();
    }

    #pragma unroll
    for (int mt = 0; mt < 2; mt++) {
        #pragma unroll
        for (int nt = 0; nt < 8; nt++) {
            int rr = m0 + wm0 + mt * 16 + (lane >> 2);
            int cc = n0 + wn0 + nt * 8 + (lane & 3) * 2;
            float b0, b1;
            if (EPI == 2) { b0 = bias[cc >> 1]; b1 = bias[FFH + (cc >> 1)]; }
            else { b0 = bias ? bias[cc] : 0.f; b1 = bias ? bias[cc + 1] : 0.f; }
            #pragma unroll
            for (int h = 0; h < 2; h++) {
                int rrow = rr + h * 8;
                float w0 = acc[mt][nt][2 * h + 0] * scale + b0;
                float w1 = acc[mt][nt][2 * h + 1] * scale + b1;
                if (EPI == 2) {
                    float ge = 0.5f * w1 * (1.f + erff(w1 * 0.70710678118654752440f));
                    ((__half*)Cv)[blockIdx.z * sC + (long long)rrow * ldc + (cc >> 1)] =
                        __float2half_rn(w0 * ge);
                } else {
                    if (relu) { w0 = fmaxf(w0, 0.f); w1 = fmaxf(w1, 0.f); }
                    if (res) {
                        const float* rp = res + (long long)(res_mod ? (rrow % res_mod) : rrow) * res_ld + cc;
                        w0 += rp[0]; w1 += rp[1];
                    }
                    if (EPI == 1)
                        *(__half2*)((__half*)Cv + blockIdx.z * sC + (long long)rrow * ldc + cc) =
                            __floats2half2_rn(w0, w1);
                    else
                        *(float2*)((float*)Cv + blockIdx.z * sC + (long long)rrow * ldc + cc) =
                            make_float2(w0, w1);
                }
            }
        }
    }
#undef ISSUE
}

// split-K reduce: av16[b*L + l, d] = fp16(sum_s partial[(s*16+b)*L*D + l*D + d])
__global__ void redk_kernel(const float* __restrict__ p, __half* __restrict__ out)
{
    long long i = (long long)blockIdx.x * 256 + threadIdx.x;   // over B*L*D
    int b = (int)(i / (L_ * D_));
    long long r = i - (long long)b * (L_ * D_);
    float s = 0.f;
    #pragma unroll
    for (int k = 0; k < 4; k++)
        s += p[((long long)(k * 16 + b)) * (L_ * D_) + r];
    out[i] = __float2half_rn(s);
}

// ---------------------------------------------------------------------------
// weight prep
// ---------------------------------------------------------------------------
__global__ void wcvt(const float* __restrict__ W, int K, int N, __half* __restrict__ out)
{
    __shared__ float t[32][33];
    int n0 = blockIdx.x * 32, k0 = blockIdx.y * 32;
    int tx = threadIdx.x, ty = threadIdx.y;
    for (int r = ty; r < 32; r += 8) t[r][tx] = W[(long long)(k0 + r) * N + n0 + tx];
    __syncthreads();
    for (int r = ty; r < 32; r += 8)
        out[(long long)(n0 + r) * K + k0 + tx] = __float2half_rn(t[tx][r]);
}

// ff_w1 [384, 3072] -> interleaved transposed [3072, 384]: row n' = 2*(n%1536) + n/1536
__global__ void wcvt_ff1(const float* __restrict__ W, __half* __restrict__ out)
{
    __shared__ float t[32][33];
    int n0 = blockIdx.x * 32, k0 = blockIdx.y * 32;
    int tx = threadIdx.x, ty = threadIdx.y;
    for (int r = ty; r < 32; r += 8) t[r][tx] = W[(long long)(k0 + r) * (2 * FFH) + n0 + tx];
    __syncthreads();
    for (int r = ty; r < 32; r += 8) {
        int n = n0 + r;
        int np = (n < FFH) ? 2 * n : 2 * (n - FFH) + 1;
        out[(long long)np * D_ + k0 + tx] = __float2half_rn(t[tx][r]);
    }
}

// V transpose fp16: kv16[B*N,768] cols 384..767 -> vt[B,384,8192]
__global__ void vtrans(const __half* __restrict__ kv, __half* __restrict__ vt)
{
    __shared__ __half t[32][34];
    int n0 = blockIdx.x * 32, d0 = blockIdx.y * 32, b = blockIdx.z;
    int tx = threadIdx.x, ty = threadIdx.y;
    const __half* src = kv + (long long)b * N_ * 768 + D_;
    for (int r = ty; r < 32; r += 8) t[r][tx] = src[(long long)(n0 + r) * 768 + d0 + tx];
    __syncthreads();
    __half* dst = vt + (long long)b * D_ * N_;
    for (int r = ty; r < 32; r += 8) dst[(long long)(d0 + r) * N_ + n0 + tx] = t[tx][r];
}

// ---------------------------------------------------------------------------
// small kernels
// ---------------------------------------------------------------------------
__global__ void mlp0_kernel(const float* __restrict__ x, const float* __restrict__ w0,
                            const float* __restrict__ b0, __half* __restrict__ out)
{
    __shared__ float sw[3 * D_];
    __shared__ float sbv[D_];
    for (int i = threadIdx.x; i < 3 * D_; i += blockDim.x) sw[i] = w0[i];
    sbv[threadIdx.x] = b0[threadIdx.x];
    __syncthreads();
    long long m = blockIdx.x;
    int n = threadIdx.x;
    float x0 = x[m * 3 + 0], x1 = x[m * 3 + 1], x2 = x[m * 3 + 2];
    float v = fmaf(x0, sw[n], fmaf(x1, sw[D_ + n], fmaf(x2, sw[2 * D_ + n], sbv[n])));
    out[m * D_ + n] = __float2half_rn(fmaxf(v, 0.f));
}

template<int IN16>
__global__ void ln_kernel(const void* __restrict__ inv, __half* __restrict__ outp,
                          const float* __restrict__ gamma, const float* __restrict__ beta)
{
    long long row = blockIdx.x;
    int t = threadIdx.x;
    float v0, v1, v2;
    if (IN16) {
        const __half* p = (const __half*)inv + row * D_;
        v0 = __half2float(p[t]); v1 = __half2float(p[t + 128]); v2 = __half2float(p[t + 256]);
    } else {
        const float* p = (const float*)inv + row * D_;
        v0 = p[t]; v1 = p[t + 128]; v2 = p[t + 256];
    }
    float s = v0 + v1 + v2;
    float sq = v0 * v0 + v1 * v1 + v2 * v2;
    #pragma unroll
    for (int o = 16; o; o >>= 1) {
        s += __shfl_xor_sync(0xffffffffu, s, o);
        sq += __shfl_xor_sync(0xffffffffu, sq, o);
    }
    __shared__ float rs[4], rq[4];
    if ((t & 31) == 0) { rs[t >> 5] = s; rq[t >> 5] = sq; }
    __syncthreads();
    float S = rs[0] + rs[1] + rs[2] + rs[3];
    float Q = rq[0] + rq[1] + rq[2] + rq[3];
    float mean = S * (1.f / (float)D_);
    float var = Q * (1.f / (float)D_) - mean * mean;
    float inv_ = rsqrtf(var + 1e-5f);
    __half* q = outp + row * D_;
    q[t]       = __float2half_rn((v0 - mean) * inv_ * gamma[t]       + beta[t]);
    q[t + 128] = __float2half_rn((v1 - mean) * inv_ * gamma[t + 128] + beta[t + 128]);
    q[t + 256] = __float2half_rn((v2 - mean) * inv_ * gamma[t + 256] + beta[t + 256]);
}

__global__ void softmax_kernel(const float* __restrict__ sim, __half* __restrict__ attn)
{
    extern __shared__ float sd[];
    __shared__ float red[8];
    long long row = blockIdx.x;
    const float* p = sim + row * (long long)N_;
    __half* q = attn + row * (long long)N_;
    int t = threadIdx.x;
    float mx = -3.4e38f;
    for (int i = t; i < N_; i += 256) { float v = p[i]; sd[i] = v; mx = fmaxf(mx, v); }
    #pragma unroll
    for (int o = 16; o; o >>= 1) mx = fmaxf(mx, __shfl_xor_sync(0xffffffffu, mx, o));
    if ((t & 31) == 0) red[t >> 5] = mx;
    __syncthreads();
    mx = red[0];
    #pragma unroll
    for (int w = 1; w < 8; w++) mx = fmaxf(mx, red[w]);
    float sum = 0.f;
    for (int i = t; i < N_; i += 256) { float e = __expf(sd[i] - mx); sd[i] = e; sum += e; }
    #pragma unroll
    for (int o = 16; o; o >>= 1) sum += __shfl_xor_sync(0xffffffffu, sum, o);
    __syncthreads();
    if ((t & 31) == 0) red[t >> 5] = sum;
    __syncthreads();
    sum = 0.f;
    #pragma unroll
    for (int w = 0; w < 8; w++) sum += red[w];
    float inv = 1.f / sum;
    for (int i = t; i < N_; i += 256) q[i] = __float2half_rn(sd[i] * inv);
}

// ---------------------------------------------------------------------------
// Launch
// ---------------------------------------------------------------------------
extern "C" void kernel_launch(void* const* d_in, const int* in_sizes, int n_in,
                              void* d_out, int out_size)
{
    const float* x        = (const float*)d_in[0];
    const float* mlp_w0   = (const float*)d_in[1];
    const float* mlp_b0   = (const float*)d_in[2];
    const float* mlp_w1   = (const float*)d_in[3];
    const float* mlp_b1   = (const float*)d_in[4];
    const float* mlp_w2   = (const float*)d_in[5];
    const float* mlp_b2   = (const float*)d_in[6];
    const float* mlp_w3   = (const float*)d_in[7];
    const float* mlp_b3   = (const float*)d_in[8];
    const float* query    = (const float*)d_in[9];
    const float* ln_q_g   = (const float*)d_in[10];
    const float* ln_q_b   = (const float*)d_in[11];
    const float* ln_ctx_g = (const float*)d_in[12];
    const float* ln_ctx_b = (const float*)d_in[13];
    const float* wq       = (const float*)d_in[14];
    const float* wkv      = (const float*)d_in[15];
    const float* wo       = (const float*)d_in[16];
    const float* bo       = (const float*)d_in[17];
    const float* ln_ff_g  = (const float*)d_in[18];
    const float* ln_ff_b  = (const float*)d_in[19];
    const float* ff_w1    = (const float*)d_in[20];
    const float* ff_b1    = (const float*)d_in[21];
    const float* ff_w2    = (const float*)d_in[22];
    const float* ff_b2    = (const float*)d_in[23];

    static __half *hA = 0, *hB = 0, *kv16 = 0, *attn16 = 0, *qn16 = 0, *q16 = 0,
                  *av16 = 0, *fn16 = 0, *gg16 = 0, *wh = 0;
    static float *sim = 0, *x1 = 0;
    if (!hA) {
        cudaGetSymbolAddress((void**)&hA, g_h16a);
        cudaGetSymbolAddress((void**)&hB, g_h16b);
        cudaGetSymbolAddress((void**)&kv16, g_kv16);
        cudaGetSymbolAddress((void**)&attn16, g_attn16);
        cudaGetSymbolAddress((void**)&qn16, g_qn16);
        cudaGetSymbolAddress((void**)&q16, g_q16);
        cudaGetSymbolAddress((void**)&av16, g_av16);
        cudaGetSymbolAddress((void**)&fn16, g_fn16);
        cudaGetSymbolAddress((void**)&gg16, g_gg16);
        cudaGetSymbolAddress((void**)&wh, g_wh);
        cudaGetSymbolAddress((void**)&sim, g_sim);
        cudaGetSymbolAddress((void**)&x1, g_x1);
        cudaFuncSetAttribute((const void*)gemm_h<0,0>, cudaFuncAttributeMaxDynamicSharedMemorySize, SMEM_BYTES);
        cudaFuncSetAttribute((const void*)gemm_h<1,0>, cudaFuncAttributeMaxDynamicSharedMemorySize, SMEM_BYTES);
        cudaFuncSetAttribute((const void*)gemm_h<2,0>, cudaFuncAttributeMaxDynamicSharedMemorySize, SMEM_BYTES);
        cudaFuncSetAttribute((const void*)gemm_h<0,2048>, cudaFuncAttributeMaxDynamicSharedMemorySize, SMEM_BYTES);
    }
    __half* vt = hB;  // reuse after ctx consumed

    dim3 tb(32, 8);
    // launch order arranged so launch index 5 (ncu -s 5 -c 1) is a big GEMM
    wcvt<<<dim3(12, 12), tb>>>(mlp_w1, D_, D_, wh + W1OFF);            // 0
    mlp0_kernel<<<MCTX, D_>>>(x, mlp_w0, mlp_b0, hA);                  // 1
    wcvt<<<dim3(12, 12), tb>>>(mlp_w2, D_, D_, wh + W2OFF);            // 2
    wcvt<<<dim3(12, 12), tb>>>(mlp_w3, D_, D_, wh + W3OFF);            // 3
    wcvt<<<dim3(12, 12), tb>>>(wq, D_, D_, wh + WQOFF);                // 4
    gemm_h<1,0><<<dim3(3, MCTX / 128), 256, SMEM_BYTES>>>(             // 5  <-- profiled
        hA, D_, 0, wh + W1OFF, D_, 0, hB, D_, 0, D_, mlp_b1, 1, 0, 0, 0, 1.f);
    wcvt<<<dim3(24, 12), tb>>>(wkv, D_, 2 * D_, wh + WKVOFF);          // 6
    wcvt<<<dim3(12, 12), tb>>>(wo, D_, D_, wh + WOOFF);                // 7
    wcvt_ff1<<<dim3(96, 12), tb>>>(ff_w1, wh + FF1OFF);                // 8
    wcvt<<<dim3(12, 48), tb>>>(ff_w2, FFH, D_, wh + FF2OFF);           // 9

    gemm_h<1,0><<<dim3(3, MCTX / 128), 256, SMEM_BYTES>>>(
        hB, D_, 0, wh + W2OFF, D_, 0, hA, D_, 0, D_, mlp_b2, 1, 0, 0, 0, 1.f);
    gemm_h<1,0><<<dim3(3, MCTX / 128), 256, SMEM_BYTES>>>(
        hA, D_, 0, wh + W3OFF, D_, 0, hB, D_, 0, D_, mlp_b3, 0, 0, 0, 0, 1.f);

    // LN(ctx) -> hA; KV projection
    ln_kernel<1><<<MCTX, 128>>>(hB, hA, ln_ctx_g, ln_ctx_b);
    gemm_h<1,0><<<dim3(6, MCTX / 128), 256, SMEM_BYTES>>>(
        hA, D_, 0, wh + WKVOFF, D_, 0, kv16, 2 * D_, 0, D_, 0, 0, 0, 0, 0, 1.f);
    vtrans<<<dim3(N_ / 32, D_ / 32, B_), tb>>>(kv16, vt);

    // Q path (1/sqrt(D) folded into wq GEMM)
    ln_kernel<0><<<L_, 128>>>(query, qn16, ln_q_g, ln_q_b);
    gemm_h<1,0><<<dim3(3, L_ / 128), 256, SMEM_BYTES>>>(
        qn16, D_, 0, wh + WQOFF, D_, 0, q16, D_, 0, D_, 0, 0, 0, 0, 0,
        0.05103103630798288f);

    // sim = Q @ K^T (fp32 out; scale already in Q)
    gemm_h<0,0><<<dim3(N_ / 128, L_ / 128, B_), 256, SMEM_BYTES>>>(
        q16, D_, 0, kv16, 2 * D_, (long long)N_ * 2 * D_,
        sim, N_, (long long)L_ * N_, D_, 0, 0, 0, 0, 0, 1.f);
    softmax_kernel<<<B_ * L_, 256, N_ * sizeof(float)>>>(sim, attn16);

    // out = attn @ V, split-K=4 (z = split*16 + batch), fp32 partials in sim
    gemm_h<0,2048><<<dim3(3, 4, 64), 256, SMEM_BYTES>>>(
        attn16, N_, (long long)L_ * N_, vt, N_, (long long)D_ * N_,
        sim, D_, (long long)L_ * D_, 2048, 0, 0, 0, 0, 0, 1.f);
    redk_kernel<<<(B_ * L_ * D_) / 256, 256>>>(sim, av16);

    // x1 = av @ wo + bo + broadcast(query)
    gemm_h<0,0><<<dim3(3, B_ * L_ / 128), 256, SMEM_BYTES>>>(
        av16, D_, 0, wh + WOOFF, D_, 0, x1, D_, 0, D_, bo, 0, query, L_, D_, 1.f);

    // feedforward: LN -> ff1+GEGLU fused -> ff2
    ln_kernel<0><<<B_ * L_, 128>>>(x1, fn16, ln_ff_g, ln_ff_b);
    gemm_h<2,0><<<dim3(24, B_ * L_ / 128), 256, SMEM_BYTES>>>(
        fn16, D_, 0, wh + FF1OFF, D_, 0, gg16, FFH, 0, D_, ff_b1, 0, 0, 0, 0, 1.f);
    gemm_h<0,0><<<dim3(3, B_ * L_ / 128), 256, SMEM_BYTES>>>(
        gg16, FFH, 0, wh + FF2OFF, FFH, 0, (float*)d_out, D_, 0, FFH,
        ff_b2, 0, x1, 0, D_, 1.f);
}